// round 3
// baseline (speedup 1.0000x reference)
#include <cuda_runtime.h>
#include <cuda_bf16.h>
#include <math.h>

#define BB 2
#define SS 2048
#define HH 16
#define DKx 1024
#define DVx 1024
#define BSx (BB*SS)
#define LOG2E 1.4426950408889634f

__device__ __nv_bfloat16 g_xb [BSx*DKx];
__device__ __nv_bfloat16 g_Wqb[DKx*DKx];
__device__ __nv_bfloat16 g_Wkb[DKx*DKx];
__device__ __nv_bfloat16 g_Wvb[DKx*DKx];
__device__ __nv_bfloat16 g_Wdb[DKx*DKx];
__device__ __nv_bfloat16 g_mixb[HH*DKx];
__device__ __nv_bfloat16 g_q  [BSx*DKx];
__device__ __nv_bfloat16 g_k  [BSx*DKx];
__device__ __nv_bfloat16 g_v  [BSx*DVx];
__device__ float         g_cb [BSx*HH];
__device__ __nv_bfloat16 g_ctx[BSx*DVx];
__device__ float         g_res[BSx*DVx];

static __device__ __forceinline__ unsigned sptr(const void* p){
    return (unsigned)__cvta_generic_to_shared(p);
}
static __device__ __forceinline__ void ldm4(unsigned&r0,unsigned&r1,unsigned&r2,unsigned&r3,unsigned a){
    asm volatile("ldmatrix.sync.aligned.m8n8.x4.shared.b16 {%0,%1,%2,%3},[%4];\n"
        :"=r"(r0),"=r"(r1),"=r"(r2),"=r"(r3):"r"(a));
}
static __device__ __forceinline__ void ldm4t(unsigned&r0,unsigned&r1,unsigned&r2,unsigned&r3,unsigned a){
    asm volatile("ldmatrix.sync.aligned.m8n8.x4.trans.shared.b16 {%0,%1,%2,%3},[%4];\n"
        :"=r"(r0),"=r"(r1),"=r"(r2),"=r"(r3):"r"(a));
}
static __device__ __forceinline__ void mma16816(float* c,unsigned a0,unsigned a1,unsigned a2,unsigned a3,
                                                unsigned b0,unsigned b1){
    asm volatile("mma.sync.aligned.m16n8k16.row.col.f32.bf16.bf16.f32 "
        "{%0,%1,%2,%3},{%4,%5,%6,%7},{%8,%9},{%0,%1,%2,%3};\n"
        :"+f"(c[0]),"+f"(c[1]),"+f"(c[2]),"+f"(c[3])
        :"r"(a0),"r"(a1),"r"(a2),"r"(a3),"r"(b0),"r"(b1));
}
static __device__ __forceinline__ unsigned pack2(float lo,float hi){
    __nv_bfloat162 t=__floats2bfloat162_rn(lo,hi); return *(unsigned*)&t;
}

__global__ void cvt_k(const float* __restrict__ s,__nv_bfloat16* __restrict__ d,int n){
    int i=blockIdx.x*blockDim.x+threadIdx.x;
    if(i<n) d[i]=__float2bfloat16(s[i]);
}

// C[M,1024] = A[M,1024] @ B[1024,1024]^T ; mode<2: bf16 out (+bias); mode 2: f32 out=acc+bias+resid
__global__ void __launch_bounds__(256) gemm_k(const __nv_bfloat16* __restrict__ A,
        const __nv_bfloat16* __restrict__ Bw,const float* __restrict__ bias,
        const float* __restrict__ resid,void* outp,int mode){
    __shared__ __align__(16) __nv_bfloat16 as_[128*72];
    __shared__ __align__(16) __nv_bfloat16 bs_[128*72];
    const int m0=blockIdx.x*128,n0=blockIdx.y*128;
    const int tid=threadIdx.x,wr=tid>>5,ln=tid&31,g=ln>>2,tg=ln&3;
    const unsigned asb=sptr(as_),bsb=sptr(bs_);
    float acc[64];
#pragma unroll
    for(int i=0;i<64;i++) acc[i]=0.f;
    for(int c0=0;c0<1024;c0+=64){
        __syncthreads();
#pragma unroll
        for(int t=0;t<4;t++){
            int idx=tid+t*256,row=idx>>3,cv=(idx&7)*8;
            *(uint4*)((char*)as_+(row*72+cv)*2)=*(const uint4*)(A +(size_t)(m0+row)*1024+c0+cv);
            *(uint4*)((char*)bs_+(row*72+cv)*2)=*(const uint4*)(Bw+(size_t)(n0+row)*1024+c0+cv);
        }
        __syncthreads();
#pragma unroll
        for(int kk=0;kk<4;kk++){
            unsigned a0,a1,a2,a3;
            ldm4(a0,a1,a2,a3,asb+((wr*16+(ln&15))*72+kk*16+((ln>>4)<<3))*2);
#pragma unroll
            for(int nb=0;nb<8;nb++){
                unsigned b0,b1,b2,b3;
                int brow=nb*16+(ln&7)+((ln&16)?8:0),bcol=kk*16+((ln&8)?8:0);
                ldm4(b0,b1,b2,b3,bsb+(brow*72+bcol)*2);
                mma16816(acc+(2*nb  )*4,a0,a1,a2,a3,b0,b1);
                mma16816(acc+(2*nb+1)*4,a0,a1,a2,a3,b2,b3);
            }
        }
    }
    const int r0=m0+wr*16+g;
    if(mode==2){
        float* out=(float*)outp;
#pragma unroll
        for(int nf=0;nf<16;nf++){
            int col=n0+nf*8+2*tg;
            float b0=bias[col],b1=bias[col+1];
            *(float2*)(out+(size_t)r0*1024+col)=make_float2(
                acc[nf*4+0]+b0+resid[(size_t)r0*1024+col],
                acc[nf*4+1]+b1+resid[(size_t)r0*1024+col+1]);
            *(float2*)(out+(size_t)(r0+8)*1024+col)=make_float2(
                acc[nf*4+2]+b0+resid[(size_t)(r0+8)*1024+col],
                acc[nf*4+3]+b1+resid[(size_t)(r0+8)*1024+col+1]);
        }
    }else{
        __nv_bfloat16* out=(__nv_bfloat16*)outp;
#pragma unroll
        for(int nf=0;nf<16;nf++){
            int col=n0+nf*8+2*tg;
            float b0=bias?bias[col]:0.f,b1=bias?bias[col+1]:0.f;
            *(__nv_bfloat162*)(out+(size_t)r0*1024+col)=__floats2bfloat162_rn(acc[nf*4+0]+b0,acc[nf*4+1]+b1);
            *(__nv_bfloat162*)(out+(size_t)(r0+8)*1024+col)=__floats2bfloat162_rn(acc[nf*4+2]+b0,acc[nf*4+3]+b1);
        }
    }
}

__global__ void __launch_bounds__(128) cb_k(const float* __restrict__ x,const float* __restrict__ Wcb){
    int s=blockIdx.x;
    __shared__ float xr[1024];
    for(int t=threadIdx.x;t<1024;t+=128) xr[t]=x[(size_t)s*1024+t];
    __syncthreads();
    int w=threadIdx.x>>5,ln=threadIdx.x&31;
#pragma unroll
    for(int j=0;j<4;j++){
        int h=w*4+j;
        const float* wrow=Wcb+(size_t)h*1024;
        float sum=0.f;
        for(int c=ln;c<1024;c+=32) sum+=xr[c]*wrow[c];
#pragma unroll
        for(int off=16;off;off>>=1) sum+=__shfl_xor_sync(0xffffffffu,sum,off);
        if(ln==0) g_cb[(size_t)s*HH+h]=sum;
    }
}

// fused attention: grid (S/128, H, B), 256 thr (8 warps x 16 q-rows)
__global__ void __launch_bounds__(256,1) flash_k(){
    const int b=blockIdx.z,h=blockIdx.y,i0=blockIdx.x*128;
    __shared__ __align__(16) __nv_bfloat16 qs [128*72];  // q chunk / V tile
    __shared__ __align__(16) __nv_bfloat16 ks_[128*72];
    __shared__ float cbs[128];
    __shared__ __align__(4) __nv_bfloat16 msh[1024];
    const int tid=threadIdx.x,wr=tid>>5,ln=tid&31,g=ln>>2,tg=ln&3;
    const unsigned qsb=sptr(qs),ksb=sptr(ks_);
    {
        const unsigned* src=(const unsigned*)(g_mixb+(size_t)h*DKx);
        unsigned* dst=(unsigned*)msh;
        for(int t=tid;t<512;t+=256) dst[t]=src[t];
    }
    float sacc[64],octx[32];
    float rm0=-1e30f,rm1=-1e30f,rl0=0.f,rl1=0.f;
#pragma unroll
    for(int i=0;i<32;i++) octx[i]=0.f;
    const __nv_bfloat16* qg=g_q+(size_t)(b*SS+i0)*DKx;
    const __nv_bfloat16* kg=g_k+(size_t)(b*SS)*DKx;
    const __nv_bfloat16* vg=g_v+(size_t)(b*SS)*DVx;
    const __nv_bfloat162* m2=(const __nv_bfloat162*)msh;

    for(int jt=0;jt<16;jt++){
        const int j0=jt*128;
#pragma unroll
        for(int i=0;i<64;i++) sacc[i]=0.f;
        for(int c0=0;c0<DKx;c0+=64){
            __syncthreads();
#pragma unroll
            for(int t=0;t<4;t++){
                int idx=tid+t*256,row=idx>>3,cv=(idx&7)*8;
                *(uint4*)((char*)qs +(row*72+cv)*2)=*(const uint4*)(qg+(size_t)row*DKx+c0+cv);
                *(uint4*)((char*)ks_+(row*72+cv)*2)=*(const uint4*)(kg+(size_t)(j0+row)*DKx+c0+cv);
            }
            if(c0==0&&tid<128) cbs[tid]=g_cb[(size_t)(b*SS+j0+tid)*HH+h];
            __syncthreads();
#pragma unroll
            for(int kk=0;kk<4;kk++){
                unsigned a0,a1,a2,a3;
                ldm4(a0,a1,a2,a3,qsb+((wr*16+(ln&15))*72+kk*16+((ln>>4)<<3))*2);
                __nv_bfloat162 mm0=m2[(c0+kk*16)/2+tg],mm1=m2[(c0+kk*16)/2+4+tg];
                {__nv_bfloat162 t=__hmul2(*(__nv_bfloat162*)&a0,mm0);a0=*(unsigned*)&t;}
                {__nv_bfloat162 t=__hmul2(*(__nv_bfloat162*)&a1,mm0);a1=*(unsigned*)&t;}
                {__nv_bfloat162 t=__hmul2(*(__nv_bfloat162*)&a2,mm1);a2=*(unsigned*)&t;}
                {__nv_bfloat162 t=__hmul2(*(__nv_bfloat162*)&a3,mm1);a3=*(unsigned*)&t;}
#pragma unroll
                for(int nb=0;nb<8;nb++){
                    unsigned b0,b1,b2,b3;
                    int brow=nb*16+(ln&7)+((ln&16)?8:0),bcol=kk*16+((ln&8)?8:0);
                    ldm4(b0,b1,b2,b3,ksb+(brow*72+bcol)*2);
                    mma16816(sacc+(2*nb  )*4,a0,a1,a2,a3,b0,b1);
                    mma16816(sacc+(2*nb+1)*4,a0,a1,a2,a3,b2,b3);
                }
            }
        }
        // online softmax: rows wr*16+g and +8; cols reduce over tg (xor 1,2)
        float mx0=rm0,mx1=rm1;
#pragma unroll
        for(int nf=0;nf<16;nf++){
            float c0v=cbs[nf*8+2*tg],c1v=cbs[nf*8+2*tg+1];
            float* sp=sacc+nf*4;
            sp[0]=(sp[0]+c0v)*0.125f; sp[1]=(sp[1]+c1v)*0.125f;
            sp[2]=(sp[2]+c0v)*0.125f; sp[3]=(sp[3]+c1v)*0.125f;
            mx0=fmaxf(mx0,fmaxf(sp[0],sp[1]));
            mx1=fmaxf(mx1,fmaxf(sp[2],sp[3]));
        }
        mx0=fmaxf(mx0,__shfl_xor_sync(0xffffffffu,mx0,1));
        mx0=fmaxf(mx0,__shfl_xor_sync(0xffffffffu,mx0,2));
        mx1=fmaxf(mx1,__shfl_xor_sync(0xffffffffu,mx1,1));
        mx1=fmaxf(mx1,__shfl_xor_sync(0xffffffffu,mx1,2));
        float al0=exp2f((rm0-mx0)*LOG2E),al1=exp2f((rm1-mx1)*LOG2E);
        rm0=mx0; rm1=mx1;
        float ls0=0.f,ls1=0.f;
#pragma unroll
        for(int nf=0;nf<16;nf++){
            float* sp=sacc+nf*4;
            sp[0]=exp2f((sp[0]-mx0)*LOG2E); ls0+=sp[0];
            sp[1]=exp2f((sp[1]-mx0)*LOG2E); ls0+=sp[1];
            sp[2]=exp2f((sp[2]-mx1)*LOG2E); ls1+=sp[2];
            sp[3]=exp2f((sp[3]-mx1)*LOG2E); ls1+=sp[3];
        }
        ls0+=__shfl_xor_sync(0xffffffffu,ls0,1);
        ls0+=__shfl_xor_sync(0xffffffffu,ls0,2);
        ls1+=__shfl_xor_sync(0xffffffffu,ls1,1);
        ls1+=__shfl_xor_sync(0xffffffffu,ls1,2);
        rl0=rl0*al0+ls0; rl1=rl1*al1+ls1;
#pragma unroll
        for(int i=0;i<8;i++){
            octx[i*4+0]*=al0; octx[i*4+1]*=al0;
            octx[i*4+2]*=al1; octx[i*4+3]*=al1;
        }
        // V tile (head slice, 128x64) into qs; ctx += P @ V
        __syncthreads();
#pragma unroll
        for(int t=0;t<4;t++){
            int idx=tid+t*256,row=idx>>3,cv=(idx&7)*8;
            *(uint4*)((char*)qs+(row*72+cv)*2)=*(const uint4*)(vg+(size_t)(j0+row)*DVx+h*64+cv);
        }
        __syncthreads();
#pragma unroll
        for(int kb=0;kb<8;kb++){
            unsigned a0=pack2(sacc[(2*kb)*4+0],sacc[(2*kb)*4+1]);
            unsigned a1=pack2(sacc[(2*kb)*4+2],sacc[(2*kb)*4+3]);
            unsigned a2=pack2(sacc[(2*kb+1)*4+0],sacc[(2*kb+1)*4+1]);
            unsigned a3=pack2(sacc[(2*kb+1)*4+2],sacc[(2*kb+1)*4+3]);
#pragma unroll
            for(int vp=0;vp<4;vp++){
                unsigned b0,b1,b2,b3;
                int vrow=kb*16+(ln&7)+((ln&8)?8:0),vcol=vp*16+((ln&16)?8:0);
                ldm4t(b0,b1,b2,b3,qsb+(vrow*72+vcol)*2);
                mma16816(octx+(2*vp  )*4,a0,a1,a2,a3,b0,b1);
                mma16816(octx+(2*vp+1)*4,a0,a1,a2,a3,b2,b3);
            }
        }
    }
    float inv0=1.f/rl0,inv1=1.f/rl1;
    int r0=i0+wr*16+g;
    __nv_bfloat16* cg=g_ctx+(size_t)(b*SS)*DVx+h*64;
#pragma unroll
    for(int nb=0;nb<8;nb++){
        int col=nb*8+2*tg;
        *(__nv_bfloat162*)(cg+(size_t)r0*DVx+col)=
            __floats2bfloat162_rn(octx[nb*4+0]*inv0,octx[nb*4+1]*inv0);
        *(__nv_bfloat162*)(cg+(size_t)(r0+8)*DVx+col)=
            __floats2bfloat162_rn(octx[nb*4+2]*inv1,octx[nb*4+3]*inv1);
    }
}

__global__ void __launch_bounds__(256) ln_k(const float* __restrict__ gamma,
        const float* __restrict__ beta,float* __restrict__ out){
    int s=blockIdx.x,tid=threadIdx.x;
    const float* r=g_res+(size_t)s*1024;
    float sum=0.f,sq=0.f;
#pragma unroll
    for(int i=tid;i<1024;i+=256){ float v=r[i]; sum+=v; sq+=v*v; }
#pragma unroll
    for(int off=16;off;off>>=1){
        sum+=__shfl_xor_sync(0xffffffffu,sum,off);
        sq +=__shfl_xor_sync(0xffffffffu,sq ,off);
    }
    __shared__ float ss[8],sv[8];
    if((tid&31)==0){ ss[tid>>5]=sum; sv[tid>>5]=sq; }
    __syncthreads();
    float tot=0.f,tot2=0.f;
#pragma unroll
    for(int i=0;i<8;i++){ tot+=ss[i]; tot2+=sv[i]; }
    float mu=tot*(1.f/1024.f),var=tot2*(1.f/1024.f)-mu*mu;
    float is=rsqrtf(var+1e-5f);
    for(int i=tid;i<1024;i+=256)
        out[(size_t)s*1024+i]=(r[i]-mu)*is*gamma[i]+beta[i];
}

extern "C" void kernel_launch(void* const* d_in,const int* in_sizes,int n_in,
                              void* d_out,int out_size){
    const float* x    =(const float*)d_in[0];
    const float* Wq   =(const float*)d_in[1];
    const float* Wk   =(const float*)d_in[2];
    const float* Wcb  =(const float*)d_in[3];
    const float* Wv   =(const float*)d_in[4];
    const float* bv   =(const float*)d_in[5];
    const float* mixing=(const float*)d_in[6];
    const float* Wd   =(const float*)d_in[7];
    const float* bd   =(const float*)d_in[8];
    const float* gamma=(const float*)d_in[9];
    const float* beta =(const float*)d_in[10];
    float* out=(float*)d_out;

    void *xb,*wqb,*wkb,*wvb,*wdb,*mixb,*qb,*kb,*vb,*ctxb,*resp;
    cudaGetSymbolAddress(&xb ,g_xb );
    cudaGetSymbolAddress(&wqb,g_Wqb);
    cudaGetSymbolAddress(&wkb,g_Wkb);
    cudaGetSymbolAddress(&wvb,g_Wvb);
    cudaGetSymbolAddress(&wdb,g_Wdb);
    cudaGetSymbolAddress(&mixb,g_mixb);
    cudaGetSymbolAddress(&qb ,g_q  );
    cudaGetSymbolAddress(&kb ,g_k  );
    cudaGetSymbolAddress(&vb ,g_v  );
    cudaGetSymbolAddress(&ctxb,g_ctx);
    cudaGetSymbolAddress(&resp,g_res);

    cvt_k<<<16384,256>>>(x,(__nv_bfloat16*)xb,BSx*DKx);
    cvt_k<<<4096,256>>>(Wq,(__nv_bfloat16*)wqb,DKx*DKx);
    cvt_k<<<4096,256>>>(Wk,(__nv_bfloat16*)wkb,DKx*DKx);
    cvt_k<<<4096,256>>>(Wv,(__nv_bfloat16*)wvb,DKx*DKx);
    cvt_k<<<4096,256>>>(Wd,(__nv_bfloat16*)wdb,DKx*DKx);
    cvt_k<<<64,256>>>(mixing,(__nv_bfloat16*)mixb,HH*DKx);

    dim3 gg(32,8);
    gemm_k<<<gg,256>>>((const __nv_bfloat16*)xb,(const __nv_bfloat16*)wqb,nullptr,nullptr,qb,0);
    gemm_k<<<gg,256>>>((const __nv_bfloat16*)xb,(const __nv_bfloat16*)wkb,nullptr,nullptr,kb,0);
    gemm_k<<<gg,256>>>((const __nv_bfloat16*)xb,(const __nv_bfloat16*)wvb,bv,nullptr,vb,0);
    cb_k<<<BSx,128>>>(x,Wcb);
    flash_k<<<dim3(16,HH,BB),256>>>();
    gemm_k<<<gg,256>>>((const __nv_bfloat16*)ctxb,(const __nv_bfloat16*)wdb,bd,x,resp,2);
    ln_k<<<BSx,256>>>(gamma,beta,out);
}

// round 5
// speedup vs baseline: 1.7208x; 1.7208x over previous
#include <cuda_runtime.h>
#include <cuda_bf16.h>
#include <math.h>

#define BB 2
#define SS 2048
#define HH 16
#define DKx 1024
#define DVx 1024
#define BSx (BB*SS)
#define LOG2E 1.4426950408889634f

__device__ __nv_bfloat16 g_xb [BSx*DKx];
__device__ __nv_bfloat16 g_Wqb[DKx*DKx];
__device__ __nv_bfloat16 g_Wkb[DKx*DKx];
__device__ __nv_bfloat16 g_Wvb[DKx*DKx];
__device__ __nv_bfloat16 g_Wdb[DKx*DKx];
__device__ __nv_bfloat16 g_mixb[HH*DKx];
__device__ __nv_bfloat16 g_q  [BSx*DKx];
__device__ __nv_bfloat16 g_k  [BSx*DKx];
__device__ __nv_bfloat16 g_v  [BSx*DVx];
__device__ float         g_cb [BSx*HH];
__device__ __nv_bfloat16 g_ctx[BSx*DVx];
__device__ float         g_res[BSx*DVx];

static __device__ __forceinline__ unsigned sptr(const void* p){
    return (unsigned)__cvta_generic_to_shared(p);
}
static __device__ __forceinline__ void ldm4(unsigned&r0,unsigned&r1,unsigned&r2,unsigned&r3,unsigned a){
    asm volatile("ldmatrix.sync.aligned.m8n8.x4.shared.b16 {%0,%1,%2,%3},[%4];\n"
        :"=r"(r0),"=r"(r1),"=r"(r2),"=r"(r3):"r"(a));
}
static __device__ __forceinline__ void ldm4t(unsigned&r0,unsigned&r1,unsigned&r2,unsigned&r3,unsigned a){
    asm volatile("ldmatrix.sync.aligned.m8n8.x4.trans.shared.b16 {%0,%1,%2,%3},[%4];\n"
        :"=r"(r0),"=r"(r1),"=r"(r2),"=r"(r3):"r"(a));
}
static __device__ __forceinline__ void mma16816(float* c,unsigned a0,unsigned a1,unsigned a2,unsigned a3,
                                                unsigned b0,unsigned b1){
    asm volatile("mma.sync.aligned.m16n8k16.row.col.f32.bf16.bf16.f32 "
        "{%0,%1,%2,%3},{%4,%5,%6,%7},{%8,%9},{%0,%1,%2,%3};\n"
        :"+f"(c[0]),"+f"(c[1]),"+f"(c[2]),"+f"(c[3])
        :"r"(a0),"r"(a1),"r"(a2),"r"(a3),"r"(b0),"r"(b1));
}
static __device__ __forceinline__ unsigned pack2(float lo,float hi){
    __nv_bfloat162 t=__floats2bfloat162_rn(lo,hi); return *(unsigned*)&t;
}
static __device__ __forceinline__ void cpa16(unsigned d,const void* s){
    asm volatile("cp.async.cg.shared.global [%0],[%1],16;"::"r"(d),"l"(s):"memory");
}
#define CPCOMMIT() asm volatile("cp.async.commit_group;":::"memory")
#define CPWAIT(n)  asm volatile("cp.async.wait_group %0;"::"n"(n):"memory")

// ---------- one fused convert kernel (launch 0) ----------
__global__ void __launch_bounds__(256) cvt_all(const float* __restrict__ x,const float* __restrict__ wq,
        const float* __restrict__ wk,const float* __restrict__ wv,const float* __restrict__ wd,
        const float* __restrict__ mx){
    int bx=blockIdx.x; const float* s; __nv_bfloat16* d; long base;
    if(bx<4096){s=x;d=g_xb;base=bx;}
    else if(bx<5120){s=wq;d=g_Wqb;base=bx-4096;}
    else if(bx<6144){s=wk;d=g_Wkb;base=bx-5120;}
    else if(bx<7168){s=wv;d=g_Wvb;base=bx-6144;}
    else if(bx<8192){s=wd;d=g_Wdb;base=bx-7168;}
    else {s=mx;d=g_mixb;base=bx-8192;}
    size_t off=(size_t)base*1024 + threadIdx.x*4;
    float4 v=*(const float4*)(s+off);
    *(__nv_bfloat162*)(d+off)  =__floats2bfloat162_rn(v.x,v.y);
    *(__nv_bfloat162*)(d+off+2)=__floats2bfloat162_rn(v.z,v.w);
}

// ---------- bf16 GEMM via mma.sync (unchanged from passing R1) ----------
__global__ void __launch_bounds__(256) gemm_k(const __nv_bfloat16* __restrict__ A,
        const __nv_bfloat16* __restrict__ Bw,const float* __restrict__ bias,
        const float* __restrict__ resid,void* outp,int mode){
    __shared__ __align__(16) __nv_bfloat16 as_[128*72];
    __shared__ __align__(16) __nv_bfloat16 bs_[128*72];
    const int m0=blockIdx.x*128,n0=blockIdx.y*128;
    const int tid=threadIdx.x,wr=tid>>5,ln=tid&31,g=ln>>2,tg=ln&3;
    const unsigned asb=sptr(as_),bsb=sptr(bs_);
    float acc[64];
#pragma unroll
    for(int i=0;i<64;i++) acc[i]=0.f;
    for(int c0=0;c0<1024;c0+=64){
        __syncthreads();
#pragma unroll
        for(int t=0;t<4;t++){
            int idx=tid+t*256,row=idx>>3,cv=(idx&7)*8;
            *(uint4*)((char*)as_+(row*72+cv)*2)=*(const uint4*)(A +(size_t)(m0+row)*1024+c0+cv);
            *(uint4*)((char*)bs_+(row*72+cv)*2)=*(const uint4*)(Bw+(size_t)(n0+row)*1024+c0+cv);
        }
        __syncthreads();
#pragma unroll
        for(int kk=0;kk<4;kk++){
            unsigned a0,a1,a2,a3;
            ldm4(a0,a1,a2,a3,asb+((wr*16+(ln&15))*72+kk*16+((ln>>4)<<3))*2);
#pragma unroll
            for(int nb=0;nb<8;nb++){
                unsigned b0,b1,b2,b3;
                int brow=nb*16+(ln&7)+((ln&16)?8:0),bcol=kk*16+((ln&8)?8:0);
                ldm4(b0,b1,b2,b3,bsb+(brow*72+bcol)*2);
                mma16816(acc+(2*nb  )*4,a0,a1,a2,a3,b0,b1);
                mma16816(acc+(2*nb+1)*4,a0,a1,a2,a3,b2,b3);
            }
        }
    }
    const int r0=m0+wr*16+g;
    if(mode==2){
        float* out=(float*)outp;
#pragma unroll
        for(int nf=0;nf<16;nf++){
            int col=n0+nf*8+2*tg;
            float b0=bias[col],b1=bias[col+1];
            *(float2*)(out+(size_t)r0*1024+col)=make_float2(
                acc[nf*4+0]+b0+resid[(size_t)r0*1024+col],
                acc[nf*4+1]+b1+resid[(size_t)r0*1024+col+1]);
            *(float2*)(out+(size_t)(r0+8)*1024+col)=make_float2(
                acc[nf*4+2]+b0+resid[(size_t)(r0+8)*1024+col],
                acc[nf*4+3]+b1+resid[(size_t)(r0+8)*1024+col+1]);
        }
    }else{
        __nv_bfloat16* out=(__nv_bfloat16*)outp;
#pragma unroll
        for(int nf=0;nf<16;nf++){
            int col=n0+nf*8+2*tg;
            float b0=bias?bias[col]:0.f,b1=bias?bias[col+1]:0.f;
            *(__nv_bfloat162*)(out+(size_t)r0*1024+col)=__floats2bfloat162_rn(acc[nf*4+0]+b0,acc[nf*4+1]+b1);
            *(__nv_bfloat162*)(out+(size_t)(r0+8)*1024+col)=__floats2bfloat162_rn(acc[nf*4+2]+b0,acc[nf*4+3]+b1);
        }
    }
}

__global__ void __launch_bounds__(128) cb_k(const float* __restrict__ x,const float* __restrict__ Wcb){
    int s=blockIdx.x;
    __shared__ float xr[1024];
    for(int t=threadIdx.x;t<1024;t+=128) xr[t]=x[(size_t)s*1024+t];
    __syncthreads();
    int w=threadIdx.x>>5,ln=threadIdx.x&31;
#pragma unroll
    for(int j=0;j<4;j++){
        int h=w*4+j;
        const float* wrow=Wcb+(size_t)h*1024;
        float sum=0.f;
        for(int c=ln;c<1024;c+=32) sum+=xr[c]*wrow[c];
#pragma unroll
        for(int off=16;off;off>>=1) sum+=__shfl_xor_sync(0xffffffffu,sum,off);
        if(ln==0) g_cb[(size_t)s*HH+h]=sum;
    }
}

// ---------- pipelined fused attention (launch 5) ----------
// dyn smem: QS0,QS1,KS0,KS1 (18432B each), VS 18432, CBS 512, MSH 2048
#define CH   18432u
#define OQS  0u
#define OKS  36864u
#define OVS  73728u
#define OCBS 92160u
#define OMSH 92672u
#define FSM  94720

__global__ void __launch_bounds__(256,1) flash_k(){
    extern __shared__ __align__(16) char sm[];
    const int b=blockIdx.z,h=blockIdx.y,i0=blockIdx.x*128;
    const int tid=threadIdx.x,wr=tid>>5,ln=tid&31,g=ln>>2,tg=ln&3;
    const unsigned sb=sptr(sm);
    float* cbs=(float*)(sm+OCBS);
    const __nv_bfloat162* m2=(const __nv_bfloat162*)(sm+OMSH);
    {
        const unsigned* src=(const unsigned*)(g_mixb+(size_t)h*DKx);
        unsigned* dst=(unsigned*)(sm+OMSH);
        for(int t=tid;t<512;t+=256) dst[t]=src[t];
    }
    const __nv_bfloat16* qg=g_q+(size_t)(b*SS+i0)*DKx;
    const __nv_bfloat16* kg=g_k+(size_t)(b*SS)*DKx;
    const __nv_bfloat16* vg=g_v+(size_t)(b*SS)*DVx;

    float sacc[64],octx[32];
    float rm0=-1e30f,rm1=-1e30f,rl0=0.f,rl1=0.f;
#pragma unroll
    for(int i=0;i<32;i++) octx[i]=0.f;

    // issue loads of q+k chunk c into buffer bf for key tile j0
    auto issue=[&](int j0,int c,int bf){
        int c0=c*64;
#pragma unroll
        for(int t=0;t<4;t++){
            int idx=t*256+tid,row=idx>>3,cv=(idx&7)*8;
            unsigned so=(unsigned)((row*72+cv)*2);
            cpa16(sb+OQS+bf*CH+so, qg+(size_t)row*DKx+c0+cv);
            cpa16(sb+OKS+bf*CH+so, kg+(size_t)(j0+row)*DKx+c0+cv);
        }
        CPCOMMIT();
    };
    auto issueV=[&](int j0){
#pragma unroll
        for(int t=0;t<4;t++){
            int idx=t*256+tid,row=idx>>3,cv=(idx&7)*8;
            cpa16(sb+OVS+(unsigned)((row*72+cv)*2), vg+(size_t)(j0+row)*DVx+h*64+cv);
        }
        CPCOMMIT();
    };

    issue(0,0,0); issue(0,1,1);

    for(int jt=0;jt<16;jt++){
        const int j0=jt*128;
#pragma unroll
        for(int i=0;i<64;i++) sacc[i]=0.f;
        for(int c=0;c<16;c++){
            if(c==14){ CPWAIT(2); } else { CPWAIT(1); }
            __syncthreads();
            if(c==0&&tid<128) cbs[tid]=g_cb[(size_t)(b*SS+j0+tid)*HH+h];
            const unsigned qb=sb+OQS+(unsigned)(c&1)*CH, kb=sb+OKS+(unsigned)(c&1)*CH;
            const int c0=c*64;
#pragma unroll
            for(int kk=0;kk<4;kk++){
                unsigned a0,a1,a2,a3;
                ldm4(a0,a1,a2,a3,qb+((wr*16+(ln&15))*72+kk*16+((ln>>4)<<3))*2);
                __nv_bfloat162 mm0=m2[(c0+kk*16)/2+tg],mm1=m2[(c0+kk*16)/2+4+tg];
                {__nv_bfloat162 t=__hmul2(*(__nv_bfloat162*)&a0,mm0);a0=*(unsigned*)&t;}
                {__nv_bfloat162 t=__hmul2(*(__nv_bfloat162*)&a1,mm0);a1=*(unsigned*)&t;}
                {__nv_bfloat162 t=__hmul2(*(__nv_bfloat162*)&a2,mm1);a2=*(unsigned*)&t;}
                {__nv_bfloat162 t=__hmul2(*(__nv_bfloat162*)&a3,mm1);a3=*(unsigned*)&t;}
#pragma unroll
                for(int nb=0;nb<8;nb++){
                    unsigned b0,b1,b2,b3;
                    int brow=nb*16+(ln&7)+((ln&16)?8:0),bcol=kk*16+((ln&8)?8:0);
                    ldm4(b0,b1,b2,b3,kb+(brow*72+bcol)*2);
                    mma16816(sacc+(2*nb  )*4,a0,a1,a2,a3,b0,b1);
                    mma16816(sacc+(2*nb+1)*4,a0,a1,a2,a3,b2,b3);
                }
            }
            __syncthreads();
            if(c<14) issue(j0,c+2,c&1);
            if(c==13) issueV(j0);
        }
        // online softmax
        float mx0=rm0,mx1=rm1;
#pragma unroll
        for(int nf=0;nf<16;nf++){
            float c0v=cbs[nf*8+2*tg],c1v=cbs[nf*8+2*tg+1];
            float* sp=sacc+nf*4;
            sp[0]=(sp[0]+c0v)*0.125f; sp[1]=(sp[1]+c1v)*0.125f;
            sp[2]=(sp[2]+c0v)*0.125f; sp[3]=(sp[3]+c1v)*0.125f;
            mx0=fmaxf(mx0,fmaxf(sp[0],sp[1]));
            mx1=fmaxf(mx1,fmaxf(sp[2],sp[3]));
        }
        mx0=fmaxf(mx0,__shfl_xor_sync(0xffffffffu,mx0,1));
        mx0=fmaxf(mx0,__shfl_xor_sync(0xffffffffu,mx0,2));
        mx1=fmaxf(mx1,__shfl_xor_sync(0xffffffffu,mx1,1));
        mx1=fmaxf(mx1,__shfl_xor_sync(0xffffffffu,mx1,2));
        float al0=exp2f((rm0-mx0)*LOG2E),al1=exp2f((rm1-mx1)*LOG2E);
        rm0=mx0; rm1=mx1;
        float ls0=0.f,ls1=0.f;
#pragma unroll
        for(int nf=0;nf<16;nf++){
            float* sp=sacc+nf*4;
            sp[0]=exp2f((sp[0]-mx0)*LOG2E); ls0+=sp[0];
            sp[1]=exp2f((sp[1]-mx0)*LOG2E); ls0+=sp[1];
            sp[2]=exp2f((sp[2]-mx1)*LOG2E); ls1+=sp[2];
            sp[3]=exp2f((sp[3]-mx1)*LOG2E); ls1+=sp[3];
        }
        ls0+=__shfl_xor_sync(0xffffffffu,ls0,1);
        ls0+=__shfl_xor_sync(0xffffffffu,ls0,2);
        ls1+=__shfl_xor_sync(0xffffffffu,ls1,1);
        ls1+=__shfl_xor_sync(0xffffffffu,ls1,2);
        rl0=rl0*al0+ls0; rl1=rl1*al1+ls1;
#pragma unroll
        for(int i=0;i<8;i++){
            octx[i*4+0]*=al0; octx[i*4+1]*=al0;
            octx[i*4+2]*=al1; octx[i*4+3]*=al1;
        }
        // PV from prefetched V tile
        CPWAIT(0);
        __syncthreads();
#pragma unroll
        for(int kb2=0;kb2<8;kb2++){
            unsigned a0=pack2(sacc[(2*kb2)*4+0],sacc[(2*kb2)*4+1]);
            unsigned a1=pack2(sacc[(2*kb2)*4+2],sacc[(2*kb2)*4+3]);
            unsigned a2=pack2(sacc[(2*kb2+1)*4+0],sacc[(2*kb2+1)*4+1]);
            unsigned a3=pack2(sacc[(2*kb2+1)*4+2],sacc[(2*kb2+1)*4+3]);
#pragma unroll
            for(int vp=0;vp<4;vp++){
                unsigned b0,b1,b2,b3;
                int vrow=kb2*16+(ln&7)+((ln&8)?8:0),vcol=vp*16+((ln&16)?8:0);
                ldm4t(b0,b1,b2,b3,sb+OVS+(vrow*72+vcol)*2);
                mma16816(octx+(2*vp  )*4,a0,a1,a2,a3,b0,b1);
                mma16816(octx+(2*vp+1)*4,a0,a1,a2,a3,b2,b3);
            }
        }
        __syncthreads();
        if(jt<15){ issue(j0+128,0,0); issue(j0+128,1,1); }
    }
    float inv0=1.f/rl0,inv1=1.f/rl1;
    int r0=i0+wr*16+g;
    __nv_bfloat16* cg=g_ctx+(size_t)(b*SS)*DVx+h*64;
#pragma unroll
    for(int nb=0;nb<8;nb++){
        int col=nb*8+2*tg;
        *(__nv_bfloat162*)(cg+(size_t)r0*DVx+col)=
            __floats2bfloat162_rn(octx[nb*4+0]*inv0,octx[nb*4+1]*inv0);
        *(__nv_bfloat162*)(cg+(size_t)(r0+8)*DVx+col)=
            __floats2bfloat162_rn(octx[nb*4+2]*inv1,octx[nb*4+3]*inv1);
    }
}

__global__ void __launch_bounds__(256) ln_k(const float* __restrict__ gamma,
        const float* __restrict__ beta,float* __restrict__ out){
    int s=blockIdx.x,tid=threadIdx.x;
    const float* r=g_res+(size_t)s*1024;
    float sum=0.f,sq=0.f;
#pragma unroll
    for(int i=tid;i<1024;i+=256){ float v=r[i]; sum+=v; sq+=v*v; }
#pragma unroll
    for(int off=16;off;off>>=1){
        sum+=__shfl_xor_sync(0xffffffffu,sum,off);
        sq +=__shfl_xor_sync(0xffffffffu,sq ,off);
    }
    __shared__ float ss[8],sv[8];
    if((tid&31)==0){ ss[tid>>5]=sum; sv[tid>>5]=sq; }
    __syncthreads();
    float tot=0.f,tot2=0.f;
#pragma unroll
    for(int i=0;i<8;i++){ tot+=ss[i]; tot2+=sv[i]; }
    float mu=tot*(1.f/1024.f),var=tot2*(1.f/1024.f)-mu*mu;
    float is=rsqrtf(var+1e-5f);
    for(int i=tid;i<1024;i+=256)
        out[(size_t)s*1024+i]=(r[i]-mu)*is*gamma[i]+beta[i];
}

extern "C" void kernel_launch(void* const* d_in,const int* in_sizes,int n_in,
                              void* d_out,int out_size){
    const float* x    =(const float*)d_in[0];
    const float* Wq   =(const float*)d_in[1];
    const float* Wk   =(const float*)d_in[2];
    const float* Wcb  =(const float*)d_in[3];
    const float* Wv   =(const float*)d_in[4];
    const float* bv   =(const float*)d_in[5];
    const float* mixing=(const float*)d_in[6];
    const float* Wd   =(const float*)d_in[7];
    const float* bd   =(const float*)d_in[8];
    const float* gamma=(const float*)d_in[9];
    const float* beta =(const float*)d_in[10];
    float* out=(float*)d_out;

    void *xb,*wqb,*wkb,*wvb,*wdb,*qb,*kb,*vb,*ctxb,*resp;
    cudaGetSymbolAddress(&xb ,g_xb ); cudaGetSymbolAddress(&wqb,g_Wqb);
    cudaGetSymbolAddress(&wkb,g_Wkb); cudaGetSymbolAddress(&wvb,g_Wvb);
    cudaGetSymbolAddress(&wdb,g_Wdb); cudaGetSymbolAddress(&qb ,g_q  );
    cudaGetSymbolAddress(&kb ,g_k  ); cudaGetSymbolAddress(&vb ,g_v  );
    cudaGetSymbolAddress(&ctxb,g_ctx); cudaGetSymbolAddress(&resp,g_res);

    cudaFuncSetAttribute(flash_k,cudaFuncAttributeMaxDynamicSharedMemorySize,FSM);

    cvt_all<<<8208,256>>>(x,Wq,Wk,Wv,Wd,mixing);                       // 0
    dim3 gg(32,8);
    gemm_k<<<gg,256>>>((const __nv_bfloat16*)xb,(const __nv_bfloat16*)wqb,nullptr,nullptr,qb,0); // 1
    gemm_k<<<gg,256>>>((const __nv_bfloat16*)xb,(const __nv_bfloat16*)wkb,nullptr,nullptr,kb,0); // 2
    gemm_k<<<gg,256>>>((const __nv_bfloat16*)xb,(const __nv_bfloat16*)wvb,bv,nullptr,vb,0);      // 3
    cb_k<<<BSx,128>>>(x,Wcb);                                          // 4
    flash_k<<<dim3(16,HH,BB),256,FSM>>>();                             // 5  <- ncu -s 5 -c 1
    gemm_k<<<gg,256>>>((const __nv_bfloat16*)ctxb,(const __nv_bfloat16*)wdb,bd,x,resp,2);        // 6
    ln_k<<<BSx,256>>>(gamma,beta,out);                                 // 7
}

// round 6
// speedup vs baseline: 1.8002x; 1.0461x over previous
#include <cuda_runtime.h>
#include <cuda_bf16.h>
#include <math.h>

#define BB 2
#define SS 2048
#define HH 16
#define DKx 1024
#define DVx 1024
#define BSx (BB*SS)
#define LOG2E 1.4426950408889634f

__device__ __nv_bfloat16 g_xb [BSx*DKx];
__device__ __nv_bfloat16 g_Wqb[DKx*DKx];
__device__ __nv_bfloat16 g_Wkb[DKx*DKx];
__device__ __nv_bfloat16 g_Wvb[DKx*DKx];
__device__ __nv_bfloat16 g_Wdb[DKx*DKx];
__device__ __nv_bfloat16 g_mixb[HH*DKx];
__device__ __nv_bfloat16 g_q  [BSx*DKx];
__device__ __nv_bfloat16 g_k  [BSx*DKx];
__device__ __nv_bfloat16 g_v  [BSx*DVx];
__device__ float         g_cb [BSx*HH];
__device__ __nv_bfloat16 g_ctx[BSx*DVx];
__device__ float         g_res[BSx*DVx];

static __device__ __forceinline__ unsigned sptr(const void* p){
    return (unsigned)__cvta_generic_to_shared(p);
}
static __device__ __forceinline__ void ldm4(unsigned&r0,unsigned&r1,unsigned&r2,unsigned&r3,unsigned a){
    asm volatile("ldmatrix.sync.aligned.m8n8.x4.shared.b16 {%0,%1,%2,%3},[%4];\n"
        :"=r"(r0),"=r"(r1),"=r"(r2),"=r"(r3):"r"(a));
}
static __device__ __forceinline__ void ldm4t(unsigned&r0,unsigned&r1,unsigned&r2,unsigned&r3,unsigned a){
    asm volatile("ldmatrix.sync.aligned.m8n8.x4.trans.shared.b16 {%0,%1,%2,%3},[%4];\n"
        :"=r"(r0),"=r"(r1),"=r"(r2),"=r"(r3):"r"(a));
}
static __device__ __forceinline__ void mma16816(float* c,unsigned a0,unsigned a1,unsigned a2,unsigned a3,
                                                unsigned b0,unsigned b1){
    asm volatile("mma.sync.aligned.m16n8k16.row.col.f32.bf16.bf16.f32 "
        "{%0,%1,%2,%3},{%4,%5,%6,%7},{%8,%9},{%0,%1,%2,%3};\n"
        :"+f"(c[0]),"+f"(c[1]),"+f"(c[2]),"+f"(c[3])
        :"r"(a0),"r"(a1),"r"(a2),"r"(a3),"r"(b0),"r"(b1));
}
static __device__ __forceinline__ unsigned pack2(float lo,float hi){
    __nv_bfloat162 t=__floats2bfloat162_rn(lo,hi); return *(unsigned*)&t;
}
static __device__ __forceinline__ void cpa16(unsigned d,const void* s){
    asm volatile("cp.async.cg.shared.global [%0],[%1],16;"::"r"(d),"l"(s):"memory");
}
#define CPCOMMIT() asm volatile("cp.async.commit_group;":::"memory")
#define CPWAIT(n)  asm volatile("cp.async.wait_group %0;"::"n"(n):"memory")

// ---------- converts ----------
__global__ void __launch_bounds__(256) cvt_main(const float* __restrict__ x,const float* __restrict__ wq,
        const float* __restrict__ wk,const float* __restrict__ wv,const float* __restrict__ wd){
    int bx=blockIdx.x; const float* s; __nv_bfloat16* d; long base;
    if(bx<4096){s=x;d=g_xb;base=bx;}
    else if(bx<5120){s=wq;d=g_Wqb;base=bx-4096;}
    else if(bx<6144){s=wk;d=g_Wkb;base=bx-5120;}
    else if(bx<7168){s=wv;d=g_Wvb;base=bx-6144;}
    else {s=wd;d=g_Wdb;base=bx-7168;}
    size_t off=(size_t)base*1024 + threadIdx.x*4;
    float4 v=*(const float4*)(s+off);
    *(__nv_bfloat162*)(d+off)  =__floats2bfloat162_rn(v.x,v.y);
    *(__nv_bfloat162*)(d+off+2)=__floats2bfloat162_rn(v.z,v.w);
}
__global__ void __launch_bounds__(256) cvt_mix(const float* __restrict__ mx){
    size_t off=(size_t)blockIdx.x*1024 + threadIdx.x*4;
    float4 v=*(const float4*)(mx+off);
    *(__nv_bfloat162*)(g_mixb+off)  =__floats2bfloat162_rn(v.x,v.y);
    *(__nv_bfloat162*)(g_mixb+off+2)=__floats2bfloat162_rn(v.z,v.w);
}

// ---------- bf16 GEMM via mma.sync ----------
__global__ void __launch_bounds__(256) gemm_k(const __nv_bfloat16* __restrict__ A,
        const __nv_bfloat16* __restrict__ Bw,const float* __restrict__ bias,
        const float* __restrict__ resid,void* outp,int mode){
    __shared__ __align__(16) __nv_bfloat16 as_[128*72];
    __shared__ __align__(16) __nv_bfloat16 bs_[128*72];
    const int m0=blockIdx.x*128,n0=blockIdx.y*128;
    const int tid=threadIdx.x,wr=tid>>5,ln=tid&31,g=ln>>2,tg=ln&3;
    const unsigned asb=sptr(as_),bsb=sptr(bs_);
    float acc[64];
#pragma unroll
    for(int i=0;i<64;i++) acc[i]=0.f;
    for(int c0=0;c0<1024;c0+=64){
        __syncthreads();
#pragma unroll
        for(int t=0;t<4;t++){
            int idx=tid+t*256,row=idx>>3,cv=(idx&7)*8;
            *(uint4*)((char*)as_+(row*72+cv)*2)=*(const uint4*)(A +(size_t)(m0+row)*1024+c0+cv);
            *(uint4*)((char*)bs_+(row*72+cv)*2)=*(const uint4*)(Bw+(size_t)(n0+row)*1024+c0+cv);
        }
        __syncthreads();
#pragma unroll
        for(int kk=0;kk<4;kk++){
            unsigned a0,a1,a2,a3;
            ldm4(a0,a1,a2,a3,asb+((wr*16+(ln&15))*72+kk*16+((ln>>4)<<3))*2);
#pragma unroll
            for(int nb=0;nb<8;nb++){
                unsigned b0,b1,b2,b3;
                int brow=nb*16+(ln&7)+((ln&16)?8:0),bcol=kk*16+((ln&8)?8:0);
                ldm4(b0,b1,b2,b3,bsb+(brow*72+bcol)*2);
                mma16816(acc+(2*nb  )*4,a0,a1,a2,a3,b0,b1);
                mma16816(acc+(2*nb+1)*4,a0,a1,a2,a3,b2,b3);
            }
        }
    }
    const int r0=m0+wr*16+g;
    if(mode==2){
        float* out=(float*)outp;
#pragma unroll
        for(int nf=0;nf<16;nf++){
            int col=n0+nf*8+2*tg;
            float b0=bias[col],b1=bias[col+1];
            *(float2*)(out+(size_t)r0*1024+col)=make_float2(
                acc[nf*4+0]+b0+resid[(size_t)r0*1024+col],
                acc[nf*4+1]+b1+resid[(size_t)r0*1024+col+1]);
            *(float2*)(out+(size_t)(r0+8)*1024+col)=make_float2(
                acc[nf*4+2]+b0+resid[(size_t)(r0+8)*1024+col],
                acc[nf*4+3]+b1+resid[(size_t)(r0+8)*1024+col+1]);
        }
    }else{
        __nv_bfloat16* out=(__nv_bfloat16*)outp;
#pragma unroll
        for(int nf=0;nf<16;nf++){
            int col=n0+nf*8+2*tg;
            float b0=bias?bias[col]:0.f,b1=bias?bias[col+1]:0.f;
            *(__nv_bfloat162*)(out+(size_t)r0*1024+col)=__floats2bfloat162_rn(acc[nf*4+0]+b0,acc[nf*4+1]+b1);
            *(__nv_bfloat162*)(out+(size_t)(r0+8)*1024+col)=__floats2bfloat162_rn(acc[nf*4+2]+b0,acc[nf*4+3]+b1);
        }
    }
}

__global__ void __launch_bounds__(128) cb_k(const float* __restrict__ x,const float* __restrict__ Wcb){
    int s=blockIdx.x;
    __shared__ float xr[1024];
    for(int t=threadIdx.x;t<1024;t+=128) xr[t]=x[(size_t)s*1024+t];
    __syncthreads();
    int w=threadIdx.x>>5,ln=threadIdx.x&31;
#pragma unroll
    for(int j=0;j<4;j++){
        int h=w*4+j;
        const float* wrow=Wcb+(size_t)h*1024;
        float sum=0.f;
        for(int c=ln;c<1024;c+=32) sum+=xr[c]*wrow[c];
#pragma unroll
        for(int off=16;off;off>>=1) sum+=__shfl_xor_sync(0xffffffffu,sum,off);
        if(ln==0) g_cb[(size_t)s*HH+h]=sum;
    }
}

// ---------- pipelined fused attention, 32x64 warp tiles ----------
#define CH   18432u
#define OQS  0u
#define OKS  36864u
#define OVS  73728u
#define OPS  92160u
#define OCBS 126976u
#define OMSH 127488u
#define ORM  129536u
#define ORL  130048u
#define OAL  130560u
#define OPX  131072u
#define FSM  132096

__global__ void __launch_bounds__(256,1) flash_k(){
    extern __shared__ __align__(16) char sm[];
    const int b=blockIdx.z,h=blockIdx.y,i0=blockIdx.x*128;
    const int tid=threadIdx.x,wr=tid>>5,ln=tid&31,g=ln>>2,tg=ln&3;
    const int mg=wr&3,nh=wr>>2;
    const unsigned sb=sptr(sm);
    float* cbs=(float*)(sm+OCBS);
    float* rmS=(float*)(sm+ORM);
    float* rlS=(float*)(sm+ORL);
    float* alS=(float*)(sm+OAL);
    float* px =(float*)(sm+OPX);
    const __nv_bfloat162* m2=(const __nv_bfloat162*)(sm+OMSH);
    {
        const unsigned* src=(const unsigned*)(g_mixb+(size_t)h*DKx);
        unsigned* dst=(unsigned*)(sm+OMSH);
        for(int t=tid;t<512;t+=256) dst[t]=src[t];
    }
    if(tid<128){ rmS[tid]=-1e30f; rlS[tid]=0.f; }
    const __nv_bfloat16* qg=g_q+(size_t)(b*SS+i0)*DKx;
    const __nv_bfloat16* kg=g_k+(size_t)(b*SS)*DKx;
    const __nv_bfloat16* vg=g_v+(size_t)(b*SS)*DVx;

    float sacc[64],octx[32];
#pragma unroll
    for(int i=0;i<32;i++) octx[i]=0.f;

    auto issue=[&](int j0,int c,int bf){
        int c0=c*64;
#pragma unroll
        for(int t=0;t<4;t++){
            int idx=t*256+tid,row=idx>>3,cv=(idx&7)*8;
            unsigned so=(unsigned)((row*72+cv)*2);
            cpa16(sb+OQS+bf*CH+so, qg+(size_t)row*DKx+c0+cv);
            cpa16(sb+OKS+bf*CH+so, kg+(size_t)(j0+row)*DKx+c0+cv);
        }
        CPCOMMIT();
    };
    auto issueV=[&](int j0){
#pragma unroll
        for(int t=0;t<4;t++){
            int idx=t*256+tid,row=idx>>3,cv=(idx&7)*8;
            cpa16(sb+OVS+(unsigned)((row*72+cv)*2), vg+(size_t)(j0+row)*DVx+h*64+cv);
        }
        CPCOMMIT();
    };

    issue(0,0,0); issue(0,1,1);

    for(int jt=0;jt<16;jt++){
        const int j0=jt*128;
#pragma unroll
        for(int i=0;i<64;i++) sacc[i]=0.f;
        for(int c=0;c<16;c++){
            if(c==14){ CPWAIT(2); } else { CPWAIT(1); }
            __syncthreads();
            if(c==0&&tid<128) cbs[tid]=g_cb[(size_t)(b*SS+j0+tid)*HH+h];
            const unsigned qb=sb+OQS+(unsigned)(c&1)*CH, kb=sb+OKS+(unsigned)(c&1)*CH;
            const int c0=c*64;
#pragma unroll
            for(int kk=0;kk<4;kk++){
                unsigned a[2][4];
                __nv_bfloat162 mm0=m2[(c0+kk*16)/2+tg],mm1=m2[(c0+kk*16)/2+4+tg];
#pragma unroll
                for(int af=0;af<2;af++){
                    unsigned x0,x1,x2,x3;
                    ldm4(x0,x1,x2,x3,qb+((mg*32+af*16+(ln&15))*72+kk*16+((ln>>4)<<3))*2);
                    {__nv_bfloat162 t=__hmul2(*(__nv_bfloat162*)&x0,mm0);x0=*(unsigned*)&t;}
                    {__nv_bfloat162 t=__hmul2(*(__nv_bfloat162*)&x1,mm0);x1=*(unsigned*)&t;}
                    {__nv_bfloat162 t=__hmul2(*(__nv_bfloat162*)&x2,mm1);x2=*(unsigned*)&t;}
                    {__nv_bfloat162 t=__hmul2(*(__nv_bfloat162*)&x3,mm1);x3=*(unsigned*)&t;}
                    a[af][0]=x0;a[af][1]=x1;a[af][2]=x2;a[af][3]=x3;
                }
#pragma unroll
                for(int nb=0;nb<4;nb++){
                    unsigned b0,b1,b2,b3;
                    int brow=nh*64+nb*16+(ln&7)+((ln&16)?8:0),bcol=kk*16+((ln&8)?8:0);
                    ldm4(b0,b1,b2,b3,kb+(brow*72+bcol)*2);
#pragma unroll
                    for(int af=0;af<2;af++){
                        mma16816(sacc+((af*4+nb)*2  )*4,a[af][0],a[af][1],a[af][2],a[af][3],b0,b1);
                        mma16816(sacc+((af*4+nb)*2+1)*4,a[af][0],a[af][1],a[af][2],a[af][3],b2,b3);
                    }
                }
            }
            __syncthreads();
            if(c<14) issue(j0,c+2,c&1);
            if(c==13) issueV(j0);
        }
        // bias+scale, local rowmax over this warp's 64 cols
        float lm[2][2]={{-1e30f,-1e30f},{-1e30f,-1e30f}};
#pragma unroll
        for(int af=0;af<2;af++)
#pragma unroll
        for(int nb=0;nb<4;nb++)
#pragma unroll
        for(int p=0;p<2;p++){
            int col=nh*64+nb*16+p*8+2*tg;
            float cb0=cbs[col],cb1=cbs[col+1];
            float* sp=sacc+((af*4+nb)*2+p)*4;
            sp[0]=(sp[0]+cb0)*0.125f; sp[1]=(sp[1]+cb1)*0.125f;
            sp[2]=(sp[2]+cb0)*0.125f; sp[3]=(sp[3]+cb1)*0.125f;
            lm[af][0]=fmaxf(lm[af][0],fmaxf(sp[0],sp[1]));
            lm[af][1]=fmaxf(lm[af][1],fmaxf(sp[2],sp[3]));
        }
#pragma unroll
        for(int af=0;af<2;af++)
#pragma unroll
        for(int hf=0;hf<2;hf++){
            lm[af][hf]=fmaxf(lm[af][hf],__shfl_xor_sync(0xffffffffu,lm[af][hf],1));
            lm[af][hf]=fmaxf(lm[af][hf],__shfl_xor_sync(0xffffffffu,lm[af][hf],2));
            if(tg==0) px[nh*128+mg*32+af*16+hf*8+g]=lm[af][hf];
        }
        __syncthreads();
        if(nh==0&&tg==0){
#pragma unroll
            for(int af=0;af<2;af++)
#pragma unroll
            for(int hf=0;hf<2;hf++){
                int row=mg*32+af*16+hf*8+g;
                float mn=fmaxf(rmS[row],fmaxf(px[row],px[128+row]));
                alS[row]=exp2f((rmS[row]-mn)*LOG2E);
                rmS[row]=mn;
            }
        }
        __syncthreads();
        // exp, row sums, pack P -> smem
        float ls[2][2]={{0.f,0.f},{0.f,0.f}};
#pragma unroll
        for(int af=0;af<2;af++){
            int r0=mg*32+af*16+g;
            float mx0=rmS[r0],mx1=rmS[r0+8];
#pragma unroll
            for(int nb=0;nb<4;nb++)
#pragma unroll
            for(int p=0;p<2;p++){
                float* sp=sacc+((af*4+nb)*2+p)*4;
                sp[0]=exp2f((sp[0]-mx0)*LOG2E); sp[1]=exp2f((sp[1]-mx0)*LOG2E);
                sp[2]=exp2f((sp[2]-mx1)*LOG2E); sp[3]=exp2f((sp[3]-mx1)*LOG2E);
                ls[af][0]+=sp[0]+sp[1]; ls[af][1]+=sp[2]+sp[3];
                int col=nh*64+nb*16+p*8+2*tg;
                *(unsigned*)(sm+OPS+((size_t)r0*136+col)*2)    =pack2(sp[0],sp[1]);
                *(unsigned*)(sm+OPS+((size_t)(r0+8)*136+col)*2)=pack2(sp[2],sp[3]);
            }
        }
#pragma unroll
        for(int af=0;af<2;af++)
#pragma unroll
        for(int hf=0;hf<2;hf++){
            ls[af][hf]+=__shfl_xor_sync(0xffffffffu,ls[af][hf],1);
            ls[af][hf]+=__shfl_xor_sync(0xffffffffu,ls[af][hf],2);
            if(tg==0) px[nh*128+mg*32+af*16+hf*8+g]=ls[af][hf];
        }
        __syncthreads();
        if(nh==0&&tg==0){
#pragma unroll
            for(int af=0;af<2;af++)
#pragma unroll
            for(int hf=0;hf<2;hf++){
                int row=mg*32+af*16+hf*8+g;
                rlS[row]=rlS[row]*alS[row]+px[row]+px[128+row];
            }
        }
        // rescale octx (PV row ownership: wr*16+g, +8)
        {
            float a0=alS[wr*16+g],a1=alS[wr*16+8+g];
#pragma unroll
            for(int i=0;i<8;i++){
                octx[i*4+0]*=a0; octx[i*4+1]*=a0;
                octx[i*4+2]*=a1; octx[i*4+3]*=a1;
            }
        }
        CPWAIT(0);
        __syncthreads();
#pragma unroll
        for(int kb2=0;kb2<8;kb2++){
            unsigned p0,p1,p2,p3;
            ldm4(p0,p1,p2,p3,sb+OPS+((wr*16+(ln&15))*136+kb2*16+((ln>>4)<<3))*2);
#pragma unroll
            for(int vp=0;vp<4;vp++){
                unsigned b0,b1,b2,b3;
                int vrow=kb2*16+(ln&7)+((ln&8)?8:0),vcol=vp*16+((ln&16)?8:0);
                ldm4t(b0,b1,b2,b3,sb+OVS+(vrow*72+vcol)*2);
                mma16816(octx+(2*vp  )*4,p0,p1,p2,p3,b0,b1);
                mma16816(octx+(2*vp+1)*4,p0,p1,p2,p3,b2,b3);
            }
        }
        __syncthreads();
        if(jt<15){ issue(j0+128,0,0); issue(j0+128,1,1); }
    }
    float inv0=1.f/rlS[wr*16+g],inv1=1.f/rlS[wr*16+8+g];
    int r0=i0+wr*16+g;
    __nv_bfloat16* cg=g_ctx+(size_t)(b*SS)*DVx+h*64;
#pragma unroll
    for(int nb=0;nb<8;nb++){
        int col=nb*8+2*tg;
        *(__nv_bfloat162*)(cg+(size_t)r0*DVx+col)=
            __floats2bfloat162_rn(octx[nb*4+0]*inv0,octx[nb*4+1]*inv0);
        *(__nv_bfloat162*)(cg+(size_t)(r0+8)*DVx+col)=
            __floats2bfloat162_rn(octx[nb*4+2]*inv1,octx[nb*4+3]*inv1);
    }
}

__global__ void __launch_bounds__(256) ln_k(const float* __restrict__ gamma,
        const float* __restrict__ beta,float* __restrict__ out){
    int s=blockIdx.x,tid=threadIdx.x;
    const float* r=g_res+(size_t)s*1024;
    float sum=0.f,sq=0.f;
#pragma unroll
    for(int i=tid;i<1024;i+=256){ float v=r[i]; sum+=v; sq+=v*v; }
#pragma unroll
    for(int off=16;off;off>>=1){
        sum+=__shfl_xor_sync(0xffffffffu,sum,off);
        sq +=__shfl_xor_sync(0xffffffffu,sq ,off);
    }
    __shared__ float ss[8],sv[8];
    if((tid&31)==0){ ss[tid>>5]=sum; sv[tid>>5]=sq; }
    __syncthreads();
    float tot=0.f,tot2=0.f;
#pragma unroll
    for(int i=0;i<8;i++){ tot+=ss[i]; tot2+=sv[i]; }
    float mu=tot*(1.f/1024.f),var=tot2*(1.f/1024.f)-mu*mu;
    float is=rsqrtf(var+1e-5f);
    for(int i=tid;i<1024;i+=256)
        out[(size_t)s*1024+i]=(r[i]-mu)*is*gamma[i]+beta[i];
}

extern "C" void kernel_launch(void* const* d_in,const int* in_sizes,int n_in,
                              void* d_out,int out_size){
    const float* x    =(const float*)d_in[0];
    const float* Wq   =(const float*)d_in[1];
    const float* Wk   =(const float*)d_in[2];
    const float* Wcb  =(const float*)d_in[3];
    const float* Wv   =(const float*)d_in[4];
    const float* bv   =(const float*)d_in[5];
    const float* mixing=(const float*)d_in[6];
    const float* Wd   =(const float*)d_in[7];
    const float* bd   =(const float*)d_in[8];
    const float* gamma=(const float*)d_in[9];
    const float* beta =(const float*)d_in[10];
    float* out=(float*)d_out;

    void *xb,*wqb,*wkb,*wvb,*wdb,*qb,*kb,*vb,*ctxb,*resp;
    cudaGetSymbolAddress(&xb ,g_xb ); cudaGetSymbolAddress(&wqb,g_Wqb);
    cudaGetSymbolAddress(&wkb,g_Wkb); cudaGetSymbolAddress(&wvb,g_Wvb);
    cudaGetSymbolAddress(&wdb,g_Wdb); cudaGetSymbolAddress(&qb ,g_q  );
    cudaGetSymbolAddress(&kb ,g_k  ); cudaGetSymbolAddress(&vb ,g_v  );
    cudaGetSymbolAddress(&ctxb,g_ctx); cudaGetSymbolAddress(&resp,g_res);

    cudaFuncSetAttribute(flash_k,cudaFuncAttributeMaxDynamicSharedMemorySize,FSM);

    cvt_main<<<8192,256>>>(x,Wq,Wk,Wv,Wd);                             // 0
    dim3 gg(32,8);
    gemm_k<<<gg,256>>>((const __nv_bfloat16*)xb,(const __nv_bfloat16*)wqb,nullptr,nullptr,qb,0); // 1
    gemm_k<<<gg,256>>>((const __nv_bfloat16*)xb,(const __nv_bfloat16*)wkb,nullptr,nullptr,kb,0); // 2
    gemm_k<<<gg,256>>>((const __nv_bfloat16*)xb,(const __nv_bfloat16*)wvb,bv,nullptr,vb,0);      // 3
    cb_k<<<BSx,128>>>(x,Wcb);                                          // 4
    cvt_mix<<<16,256>>>(mixing);                                       // 5
    flash_k<<<dim3(16,HH,BB),256,FSM>>>();                             // 6  <- target of ncu
    gemm_k<<<gg,256>>>((const __nv_bfloat16*)ctxb,(const __nv_bfloat16*)wdb,bd,x,resp,2);        // 7
    ln_k<<<BSx,256>>>(gamma,beta,out);                                 // 8
}

// round 7
// speedup vs baseline: 1.8323x; 1.0178x over previous
#include <cuda_runtime.h>
#include <cuda_bf16.h>
#include <math.h>

#define BB 2
#define SS 2048
#define HH 16
#define DKx 1024
#define DVx 1024
#define BSx (BB*SS)
#define LOG2E 1.4426950408889634f

__device__ __nv_bfloat16 g_xb [BSx*DKx];
__device__ __nv_bfloat16 g_Wqb[DKx*DKx];
__device__ __nv_bfloat16 g_Wkb[DKx*DKx];
__device__ __nv_bfloat16 g_Wvb[DKx*DKx];
__device__ __nv_bfloat16 g_Wdb[DKx*DKx];
__device__ __nv_bfloat16 g_mixb[HH*DKx];
__device__ __nv_bfloat16 g_q  [BSx*DKx];
__device__ __nv_bfloat16 g_k  [BSx*DKx];
__device__ __nv_bfloat16 g_v  [BSx*DVx];
__device__ unsigned char g_q8 [(size_t)HH*BSx*DKx];
__device__ unsigned char g_k8 [(size_t)BSx*DKx];
__device__ float         g_cb [BSx*HH];
__device__ __nv_bfloat16 g_ctx[BSx*DVx];
__device__ float         g_res[BSx*DVx];

static __device__ __forceinline__ unsigned sptr(const void* p){
    return (unsigned)__cvta_generic_to_shared(p);
}
static __device__ __forceinline__ void ldm4(unsigned&r0,unsigned&r1,unsigned&r2,unsigned&r3,unsigned a){
    asm volatile("ldmatrix.sync.aligned.m8n8.x4.shared.b16 {%0,%1,%2,%3},[%4];\n"
        :"=r"(r0),"=r"(r1),"=r"(r2),"=r"(r3):"r"(a));
}
static __device__ __forceinline__ void ldm4t(unsigned&r0,unsigned&r1,unsigned&r2,unsigned&r3,unsigned a){
    asm volatile("ldmatrix.sync.aligned.m8n8.x4.trans.shared.b16 {%0,%1,%2,%3},[%4];\n"
        :"=r"(r0),"=r"(r1),"=r"(r2),"=r"(r3):"r"(a));
}
static __device__ __forceinline__ void mma16816(float* c,unsigned a0,unsigned a1,unsigned a2,unsigned a3,
                                                unsigned b0,unsigned b1){
    asm volatile("mma.sync.aligned.m16n8k16.row.col.f32.bf16.bf16.f32 "
        "{%0,%1,%2,%3},{%4,%5,%6,%7},{%8,%9},{%0,%1,%2,%3};\n"
        :"+f"(c[0]),"+f"(c[1]),"+f"(c[2]),"+f"(c[3])
        :"r"(a0),"r"(a1),"r"(a2),"r"(a3),"r"(b0),"r"(b1));
}
static __device__ __forceinline__ void mma16832(float* c,unsigned a0,unsigned a1,unsigned a2,unsigned a3,
                                                unsigned b0,unsigned b1){
    asm volatile("mma.sync.aligned.m16n8k32.row.col.f32.e4m3.e4m3.f32 "
        "{%0,%1,%2,%3},{%4,%5,%6,%7},{%8,%9},{%0,%1,%2,%3};\n"
        :"+f"(c[0]),"+f"(c[1]),"+f"(c[2]),"+f"(c[3])
        :"r"(a0),"r"(a1),"r"(a2),"r"(a3),"r"(b0),"r"(b1));
}
static __device__ __forceinline__ unsigned pack2(float lo,float hi){
    __nv_bfloat162 t=__floats2bfloat162_rn(lo,hi); return *(unsigned*)&t;
}
static __device__ __forceinline__ unsigned pk8(float f0,float f1,float f2,float f3){
    unsigned r;
    asm("{\n\t.reg .b16 lo,hi;\n\t"
        "cvt.rn.satfinite.e4m3x2.f32 lo, %2, %1;\n\t"
        "cvt.rn.satfinite.e4m3x2.f32 hi, %4, %3;\n\t"
        "mov.b32 %0,{lo,hi};\n\t}"
        :"=r"(r):"f"(f0),"f"(f1),"f"(f2),"f"(f3));
    return r;
}
static __device__ __forceinline__ void cpa16(unsigned d,const void* s){
    asm volatile("cp.async.cg.shared.global [%0],[%1],16;"::"r"(d),"l"(s):"memory");
}
#define CPCOMMIT() asm volatile("cp.async.commit_group;":::"memory")
#define CPWAIT(n)  asm volatile("cp.async.wait_group %0;"::"n"(n):"memory")

// ---------- launch 0: all converts ----------
__global__ void __launch_bounds__(256) cvt_all(const float* __restrict__ x,const float* __restrict__ wq,
        const float* __restrict__ wk,const float* __restrict__ wv,const float* __restrict__ wd,
        const float* __restrict__ mx){
    int bx=blockIdx.x; const float* s; __nv_bfloat16* d; long base;
    if(bx<4096){s=x;d=g_xb;base=bx;}
    else if(bx<5120){s=wq;d=g_Wqb;base=bx-4096;}
    else if(bx<6144){s=wk;d=g_Wkb;base=bx-5120;}
    else if(bx<7168){s=wv;d=g_Wvb;base=bx-6144;}
    else if(bx<8192){s=wd;d=g_Wdb;base=bx-7168;}
    else {s=mx;d=g_mixb;base=bx-8192;}
    size_t off=(size_t)base*1024 + threadIdx.x*4;
    float4 v=*(const float4*)(s+off);
    *(__nv_bfloat162*)(d+off)  =__floats2bfloat162_rn(v.x,v.y);
    *(__nv_bfloat162*)(d+off+2)=__floats2bfloat162_rn(v.z,v.w);
}

// ---------- bf16 GEMM; mode 3 = batched qkv (z picks weight/out) ----------
__global__ void __launch_bounds__(256) gemm_k(const __nv_bfloat16* __restrict__ A,
        const __nv_bfloat16* __restrict__ Bw,const float* __restrict__ bias,
        const float* __restrict__ resid,void* outp,int mode){
    __shared__ __align__(16) __nv_bfloat16 as_[128*72];
    __shared__ __align__(16) __nv_bfloat16 bs_[128*72];
    if(mode==3){
        int z=blockIdx.z;
        Bw=(z==0)?g_Wqb:(z==1)?g_Wkb:g_Wvb;
        outp=(z==0)?(void*)g_q:(z==1)?(void*)g_k:(void*)g_v;
        if(z!=2) bias=nullptr;
        mode=0;
    }
    const int m0=blockIdx.x*128,n0=blockIdx.y*128;
    const int tid=threadIdx.x,wr=tid>>5,ln=tid&31,g=ln>>2,tg=ln&3;
    const unsigned asb=sptr(as_),bsb=sptr(bs_);
    float acc[64];
#pragma unroll
    for(int i=0;i<64;i++) acc[i]=0.f;
    for(int c0=0;c0<1024;c0+=64){
        __syncthreads();
#pragma unroll
        for(int t=0;t<4;t++){
            int idx=tid+t*256,row=idx>>3,cv=(idx&7)*8;
            *(uint4*)((char*)as_+(row*72+cv)*2)=*(const uint4*)(A +(size_t)(m0+row)*1024+c0+cv);
            *(uint4*)((char*)bs_+(row*72+cv)*2)=*(const uint4*)(Bw+(size_t)(n0+row)*1024+c0+cv);
        }
        __syncthreads();
#pragma unroll
        for(int kk=0;kk<4;kk++){
            unsigned a0,a1,a2,a3;
            ldm4(a0,a1,a2,a3,asb+((wr*16+(ln&15))*72+kk*16+((ln>>4)<<3))*2);
#pragma unroll
            for(int nb=0;nb<8;nb++){
                unsigned b0,b1,b2,b3;
                int brow=nb*16+(ln&7)+((ln&16)?8:0),bcol=kk*16+((ln&8)?8:0);
                ldm4(b0,b1,b2,b3,bsb+(brow*72+bcol)*2);
                mma16816(acc+(2*nb  )*4,a0,a1,a2,a3,b0,b1);
                mma16816(acc+(2*nb+1)*4,a0,a1,a2,a3,b2,b3);
            }
        }
    }
    const int r0=m0+wr*16+g;
    if(mode==2){
        float* out=(float*)outp;
#pragma unroll
        for(int nf=0;nf<16;nf++){
            int col=n0+nf*8+2*tg;
            float b0=bias[col],b1=bias[col+1];
            *(float2*)(out+(size_t)r0*1024+col)=make_float2(
                acc[nf*4+0]+b0+resid[(size_t)r0*1024+col],
                acc[nf*4+1]+b1+resid[(size_t)r0*1024+col+1]);
            *(float2*)(out+(size_t)(r0+8)*1024+col)=make_float2(
                acc[nf*4+2]+b0+resid[(size_t)(r0+8)*1024+col],
                acc[nf*4+3]+b1+resid[(size_t)(r0+8)*1024+col+1]);
        }
    }else{
        __nv_bfloat16* out=(__nv_bfloat16*)outp;
#pragma unroll
        for(int nf=0;nf<16;nf++){
            int col=n0+nf*8+2*tg;
            float b0=bias?bias[col]:0.f,b1=bias?bias[col+1]:0.f;
            *(__nv_bfloat162*)(out+(size_t)r0*1024+col)=__floats2bfloat162_rn(acc[nf*4+0]+b0,acc[nf*4+1]+b1);
            *(__nv_bfloat162*)(out+(size_t)(r0+8)*1024+col)=__floats2bfloat162_rn(acc[nf*4+2]+b0,acc[nf*4+3]+b1);
        }
    }
}

// ---------- launch 2: cb + q8mix + k8 ----------
__global__ void __launch_bounds__(256) prep8(const float* __restrict__ x,const float* __restrict__ Wcb){
    int bx=blockIdx.x,tid=threadIdx.x;
    if(bx<4096){
        __shared__ float xr[1024];
        int s=bx;
        for(int t=tid;t<1024;t+=256) xr[t]=x[(size_t)s*1024+t];
        __syncthreads();
        int w=tid>>5,ln=tid&31;
#pragma unroll
        for(int j=0;j<2;j++){
            int h=w*2+j;
            const float* wrow=Wcb+(size_t)h*1024;
            float sum=0.f;
            for(int c=ln;c<1024;c+=32) sum+=xr[c]*wrow[c];
#pragma unroll
            for(int off=16;off;off>>=1) sum+=__shfl_xor_sync(0xffffffffu,sum,off);
            if(ln==0) g_cb[(size_t)s*HH+h]=sum;
        }
    }else if(bx<8192){
        int row=bx-4096, col=tid*4;
        const __nv_bfloat162* q2=(const __nv_bfloat162*)(g_q+(size_t)row*1024+col);
        float2 q0=__bfloat1622float2(q2[0]),q1=__bfloat1622float2(q2[1]);
#pragma unroll
        for(int h=0;h<HH;h++){
            const __nv_bfloat162* m2=(const __nv_bfloat162*)(g_mixb+(size_t)h*1024+col);
            float2 m0=__bfloat1622float2(m2[0]),m1=__bfloat1622float2(m2[1]);
            unsigned p=pk8(q0.x*m0.x,q0.y*m0.y,q1.x*m1.x,q1.y*m1.y);
            *(unsigned*)(g_q8+((size_t)h*4096+row)*1024+col)=p;
        }
    }else{
        size_t off=((size_t)(bx-8192)*256+tid)*4;
        const __nv_bfloat162* k2=(const __nv_bfloat162*)(g_k+off);
        float2 k0=__bfloat1622float2(k2[0]),k1=__bfloat1622float2(k2[1]);
        *(unsigned*)(g_k8+off)=pk8(k0.x,k0.y,k1.x,k1.y);
    }
}

// ---------- launch 3: FP8-score fused attention, 32x64 warp tiles ----------
#define CH8  10240u
#define OQ8  0u
#define OK8  20480u
#define OVS  40960u
#define OPS  59392u
#define OCBS 94208u
#define ORM  94720u
#define ORL  95232u
#define OAL  95744u
#define OPX  96256u
#define FSM  97280

__global__ void __launch_bounds__(256,1) flash_k(){
    extern __shared__ __align__(16) char sm[];
    const int b=blockIdx.z,h=blockIdx.y,i0=blockIdx.x*128;
    const int tid=threadIdx.x,wr=tid>>5,ln=tid&31,g=ln>>2,tg=ln&3;
    const int mg=wr&3,nh=wr>>2;
    const unsigned sb=sptr(sm);
    float* cbs=(float*)(sm+OCBS);
    float* rmS=(float*)(sm+ORM);
    float* rlS=(float*)(sm+ORL);
    float* alS=(float*)(sm+OAL);
    float* px =(float*)(sm+OPX);
    if(tid<128){ rmS[tid]=-1e30f; rlS[tid]=0.f; }
    const unsigned char* q8g=g_q8+((size_t)h*4096+b*2048+i0)*1024;
    const unsigned char* k8g=g_k8+(size_t)(b*2048)*1024;
    const __nv_bfloat16* vg=g_v+(size_t)(b*SS)*DVx;

    float sacc[64],octx[32];
#pragma unroll
    for(int i=0;i<32;i++) octx[i]=0.f;

    auto issue=[&](int j0,int c,int bf){
        int c0=c*64;
#pragma unroll
        for(int t=0;t<2;t++){
            int idx=t*256+tid,row=idx>>2,cv=(idx&3)*16;
            unsigned so=(unsigned)(row*80+cv);
            cpa16(sb+OQ8+bf*CH8+so, q8g+(size_t)row*1024+c0+cv);
            cpa16(sb+OK8+bf*CH8+so, k8g+(size_t)(j0+row)*1024+c0+cv);
        }
        CPCOMMIT();
    };
    auto issueV=[&](int j0){
#pragma unroll
        for(int t=0;t<4;t++){
            int idx=t*256+tid,row=idx>>3,cv=(idx&7)*8;
            cpa16(sb+OVS+(unsigned)((row*72+cv)*2), vg+(size_t)(j0+row)*DVx+h*64+cv);
        }
        CPCOMMIT();
    };

    issue(0,0,0); issue(0,1,1);

    for(int jt=0;jt<16;jt++){
        const int j0=jt*128;
#pragma unroll
        for(int i=0;i<64;i++) sacc[i]=0.f;
        for(int c=0;c<16;c++){
            if(c==14){ CPWAIT(2); } else { CPWAIT(1); }
            __syncthreads();
            if(c==0&&tid<128) cbs[tid]=g_cb[(size_t)(b*SS+j0+tid)*HH+h];
            const unsigned qb=sb+OQ8+(unsigned)(c&1)*CH8, kb=sb+OK8+(unsigned)(c&1)*CH8;
#pragma unroll
            for(int kk=0;kk<2;kk++){
                unsigned a[2][4];
#pragma unroll
                for(int af=0;af<2;af++)
                    ldm4(a[af][0],a[af][1],a[af][2],a[af][3],
                         qb+(mg*32+af*16+(ln&15))*80+kk*32+((ln>>4)<<4));
#pragma unroll
                for(int nb=0;nb<4;nb++){
                    unsigned b0,b1,b2,b3;
                    int brow=nh*64+nb*16+(ln&7)+((ln&16)?8:0);
                    ldm4(b0,b1,b2,b3,kb+brow*80+kk*32+((ln&8)?16:0));
#pragma unroll
                    for(int af=0;af<2;af++){
                        mma16832(sacc+((af*4+nb)*2  )*4,a[af][0],a[af][1],a[af][2],a[af][3],b0,b1);
                        mma16832(sacc+((af*4+nb)*2+1)*4,a[af][0],a[af][1],a[af][2],a[af][3],b2,b3);
                    }
                }
            }
            __syncthreads();
            if(c<14) issue(j0,c+2,c&1);
            if(c==13) issueV(j0);
        }
        float lm[2][2]={{-1e30f,-1e30f},{-1e30f,-1e30f}};
#pragma unroll
        for(int af=0;af<2;af++)
#pragma unroll
        for(int nb=0;nb<4;nb++)
#pragma unroll
        for(int p=0;p<2;p++){
            int col=nh*64+nb*16+p*8+2*tg;
            float cb0=cbs[col],cb1=cbs[col+1];
            float* sp=sacc+((af*4+nb)*2+p)*4;
            sp[0]=(sp[0]+cb0)*0.125f; sp[1]=(sp[1]+cb1)*0.125f;
            sp[2]=(sp[2]+cb0)*0.125f; sp[3]=(sp[3]+cb1)*0.125f;
            lm[af][0]=fmaxf(lm[af][0],fmaxf(sp[0],sp[1]));
            lm[af][1]=fmaxf(lm[af][1],fmaxf(sp[2],sp[3]));
        }
#pragma unroll
        for(int af=0;af<2;af++)
#pragma unroll
        for(int hf=0;hf<2;hf++){
            lm[af][hf]=fmaxf(lm[af][hf],__shfl_xor_sync(0xffffffffu,lm[af][hf],1));
            lm[af][hf]=fmaxf(lm[af][hf],__shfl_xor_sync(0xffffffffu,lm[af][hf],2));
            if(tg==0) px[nh*128+mg*32+af*16+hf*8+g]=lm[af][hf];
        }
        __syncthreads();
        if(nh==0&&tg==0){
#pragma unroll
            for(int af=0;af<2;af++)
#pragma unroll
            for(int hf=0;hf<2;hf++){
                int row=mg*32+af*16+hf*8+g;
                float mn=fmaxf(rmS[row],fmaxf(px[row],px[128+row]));
                alS[row]=exp2f((rmS[row]-mn)*LOG2E);
                rmS[row]=mn;
            }
        }
        __syncthreads();
        float ls[2][2]={{0.f,0.f},{0.f,0.f}};
#pragma unroll
        for(int af=0;af<2;af++){
            int r0=mg*32+af*16+g;
            float mx0=rmS[r0],mx1=rmS[r0+8];
#pragma unroll
            for(int nb=0;nb<4;nb++)
#pragma unroll
            for(int p=0;p<2;p++){
                float* sp=sacc+((af*4+nb)*2+p)*4;
                sp[0]=exp2f((sp[0]-mx0)*LOG2E); sp[1]=exp2f((sp[1]-mx0)*LOG2E);
                sp[2]=exp2f((sp[2]-mx1)*LOG2E); sp[3]=exp2f((sp[3]-mx1)*LOG2E);
                ls[af][0]+=sp[0]+sp[1]; ls[af][1]+=sp[2]+sp[3];
                int col=nh*64+nb*16+p*8+2*tg;
                *(unsigned*)(sm+OPS+((size_t)r0*136+col)*2)    =pack2(sp[0],sp[1]);
                *(unsigned*)(sm+OPS+((size_t)(r0+8)*136+col)*2)=pack2(sp[2],sp[3]);
            }
        }
#pragma unroll
        for(int af=0;af<2;af++)
#pragma unroll
        for(int hf=0;hf<2;hf++){
            ls[af][hf]+=__shfl_xor_sync(0xffffffffu,ls[af][hf],1);
            ls[af][hf]+=__shfl_xor_sync(0xffffffffu,ls[af][hf],2);
            if(tg==0) px[nh*128+mg*32+af*16+hf*8+g]=ls[af][hf];
        }
        __syncthreads();
        if(nh==0&&tg==0){
#pragma unroll
            for(int af=0;af<2;af++)
#pragma unroll
            for(int hf=0;hf<2;hf++){
                int row=mg*32+af*16+hf*8+g;
                rlS[row]=rlS[row]*alS[row]+px[row]+px[128+row];
            }
        }
        {
            float a0=alS[wr*16+g],a1=alS[wr*16+8+g];
#pragma unroll
            for(int i=0;i<8;i++){
                octx[i*4+0]*=a0; octx[i*4+1]*=a0;
                octx[i*4+2]*=a1; octx[i*4+3]*=a1;
            }
        }
        CPWAIT(0);
        __syncthreads();
#pragma unroll
        for(int kb2=0;kb2<8;kb2++){
            unsigned p0,p1,p2,p3;
            ldm4(p0,p1,p2,p3,sb+OPS+((wr*16+(ln&15))*136+kb2*16+((ln>>4)<<3))*2);
#pragma unroll
            for(int vp=0;vp<4;vp++){
                unsigned b0,b1,b2,b3;
                int vrow=kb2*16+(ln&7)+((ln&8)?8:0),vcol=vp*16+((ln&16)?8:0);
                ldm4t(b0,b1,b2,b3,sb+OVS+(vrow*72+vcol)*2);
                mma16816(octx+(2*vp  )*4,p0,p1,p2,p3,b0,b1);
                mma16816(octx+(2*vp+1)*4,p0,p1,p2,p3,b2,b3);
            }
        }
        __syncthreads();
        if(jt<15){ issue(j0+128,0,0); issue(j0+128,1,1); }
    }
    float inv0=1.f/rlS[wr*16+g],inv1=1.f/rlS[wr*16+8+g];
    int r0=i0+wr*16+g;
    __nv_bfloat16* cg=g_ctx+(size_t)(b*SS)*DVx+h*64;
#pragma unroll
    for(int nb=0;nb<8;nb++){
        int col=nb*8+2*tg;
        *(__nv_bfloat162*)(cg+(size_t)r0*DVx+col)=
            __floats2bfloat162_rn(octx[nb*4+0]*inv0,octx[nb*4+1]*inv0);
        *(__nv_bfloat162*)(cg+(size_t)(r0+8)*DVx+col)=
            __floats2bfloat162_rn(octx[nb*4+2]*inv1,octx[nb*4+3]*inv1);
    }
}

__global__ void __launch_bounds__(256) ln_k(const float* __restrict__ gamma,
        const float* __restrict__ beta,float* __restrict__ out){
    int s=blockIdx.x,tid=threadIdx.x;
    const float* r=g_res+(size_t)s*1024;
    float sum=0.f,sq=0.f;
#pragma unroll
    for(int i=tid;i<1024;i+=256){ float v=r[i]; sum+=v; sq+=v*v; }
#pragma unroll
    for(int off=16;off;off>>=1){
        sum+=__shfl_xor_sync(0xffffffffu,sum,off);
        sq +=__shfl_xor_sync(0xffffffffu,sq ,off);
    }
    __shared__ float ss[8],sv[8];
    if((tid&31)==0){ ss[tid>>5]=sum; sv[tid>>5]=sq; }
    __syncthreads();
    float tot=0.f,tot2=0.f;
#pragma unroll
    for(int i=0;i<8;i++){ tot+=ss[i]; tot2+=sv[i]; }
    float mu=tot*(1.f/1024.f),var=tot2*(1.f/1024.f)-mu*mu;
    float is=rsqrtf(var+1e-5f);
    for(int i=tid;i<1024;i+=256)
        out[(size_t)s*1024+i]=(r[i]-mu)*is*gamma[i]+beta[i];
}

extern "C" void kernel_launch(void* const* d_in,const int* in_sizes,int n_in,
                              void* d_out,int out_size){
    const float* x    =(const float*)d_in[0];
    const float* Wq   =(const float*)d_in[1];
    const float* Wk   =(const float*)d_in[2];
    const float* Wcb  =(const float*)d_in[3];
    const float* Wv   =(const float*)d_in[4];
    const float* bv   =(const float*)d_in[5];
    const float* mixing=(const float*)d_in[6];
    const float* Wd   =(const float*)d_in[7];
    const float* bd   =(const float*)d_in[8];
    const float* gamma=(const float*)d_in[9];
    const float* beta =(const float*)d_in[10];
    float* out=(float*)d_out;

    void *xb,*wdb,*ctxb,*resp;
    cudaGetSymbolAddress(&xb ,g_xb ); cudaGetSymbolAddress(&wdb,g_Wdb);
    cudaGetSymbolAddress(&ctxb,g_ctx); cudaGetSymbolAddress(&resp,g_res);

    cudaFuncSetAttribute(flash_k,cudaFuncAttributeMaxDynamicSharedMemorySize,FSM);

    cvt_all<<<8208,256>>>(x,Wq,Wk,Wv,Wd,mixing);                        // 0
    gemm_k<<<dim3(32,8,3),256>>>((const __nv_bfloat16*)xb,nullptr,bv,nullptr,nullptr,3); // 1
    prep8<<<12288,256>>>(x,Wcb);                                        // 2
    flash_k<<<dim3(16,HH,BB),256,FSM>>>();                              // 3 <- profiled
    gemm_k<<<dim3(32,8),256>>>((const __nv_bfloat16*)ctxb,(const __nv_bfloat16*)wdb,bd,x,resp,2); // 4
    ln_k<<<BSx,256>>>(gamma,beta,out);                                  // 5
}

// round 8
// speedup vs baseline: 2.0167x; 1.1006x over previous
#include <cuda_runtime.h>
#include <cuda_bf16.h>
#include <math.h>

#define BB 2
#define SS 2048
#define HH 16
#define DKx 1024
#define DVx 1024
#define BSx (BB*SS)
#define LOG2E 1.4426950408889634f

__device__ __nv_bfloat16 g_xb [BSx*DKx];
__device__ __nv_bfloat16 g_Wqb[DKx*DKx];
__device__ __nv_bfloat16 g_Wkb[DKx*DKx];
__device__ __nv_bfloat16 g_Wvb[DKx*DKx];
__device__ __nv_bfloat16 g_Wdb[DKx*DKx];
__device__ __nv_bfloat16 g_mixb[HH*DKx];
__device__ __nv_bfloat16 g_q  [BSx*DKx];
__device__ __nv_bfloat16 g_k  [BSx*DKx];
__device__ __nv_bfloat16 g_v  [BSx*DVx];
__device__ unsigned char g_q8 [(size_t)HH*BSx*DKx];
__device__ unsigned char g_k8 [(size_t)BSx*DKx];
__device__ float         g_cb [BSx*HH];
__device__ __nv_bfloat16 g_ctx[BSx*DVx];
__device__ float         g_res[BSx*DVx];

static __device__ __forceinline__ unsigned sptr(const void* p){
    return (unsigned)__cvta_generic_to_shared(p);
}
static __device__ __forceinline__ void ldm4(unsigned&r0,unsigned&r1,unsigned&r2,unsigned&r3,unsigned a){
    asm volatile("ldmatrix.sync.aligned.m8n8.x4.shared.b16 {%0,%1,%2,%3},[%4];\n"
        :"=r"(r0),"=r"(r1),"=r"(r2),"=r"(r3):"r"(a));
}
static __device__ __forceinline__ void ldm4t(unsigned&r0,unsigned&r1,unsigned&r2,unsigned&r3,unsigned a){
    asm volatile("ldmatrix.sync.aligned.m8n8.x4.trans.shared.b16 {%0,%1,%2,%3},[%4];\n"
        :"=r"(r0),"=r"(r1),"=r"(r2),"=r"(r3):"r"(a));
}
static __device__ __forceinline__ void mma16816(float* c,unsigned a0,unsigned a1,unsigned a2,unsigned a3,
                                                unsigned b0,unsigned b1){
    asm volatile("mma.sync.aligned.m16n8k16.row.col.f32.bf16.bf16.f32 "
        "{%0,%1,%2,%3},{%4,%5,%6,%7},{%8,%9},{%0,%1,%2,%3};\n"
        :"+f"(c[0]),"+f"(c[1]),"+f"(c[2]),"+f"(c[3])
        :"r"(a0),"r"(a1),"r"(a2),"r"(a3),"r"(b0),"r"(b1));
}
static __device__ __forceinline__ void mma16832(float* c,unsigned a0,unsigned a1,unsigned a2,unsigned a3,
                                                unsigned b0,unsigned b1){
    asm volatile("mma.sync.aligned.m16n8k32.row.col.f32.e4m3.e4m3.f32 "
        "{%0,%1,%2,%3},{%4,%5,%6,%7},{%8,%9},{%0,%1,%2,%3};\n"
        :"+f"(c[0]),"+f"(c[1]),"+f"(c[2]),"+f"(c[3])
        :"r"(a0),"r"(a1),"r"(a2),"r"(a3),"r"(b0),"r"(b1));
}
static __device__ __forceinline__ unsigned pack2(float lo,float hi){
    __nv_bfloat162 t=__floats2bfloat162_rn(lo,hi); return *(unsigned*)&t;
}
static __device__ __forceinline__ unsigned pk8(float f0,float f1,float f2,float f3){
    unsigned r;
    asm("{\n\t.reg .b16 lo,hi;\n\t"
        "cvt.rn.satfinite.e4m3x2.f32 lo, %2, %1;\n\t"
        "cvt.rn.satfinite.e4m3x2.f32 hi, %4, %3;\n\t"
        "mov.b32 %0,{lo,hi};\n\t}"
        :"=r"(r):"f"(f0),"f"(f1),"f"(f2),"f"(f3));
    return r;
}
static __device__ __forceinline__ void cpa16(unsigned d,const void* s){
    asm volatile("cp.async.cg.shared.global [%0],[%1],16;"::"r"(d),"l"(s):"memory");
}
#define CPCOMMIT() asm volatile("cp.async.commit_group;":::"memory")
#define CPWAIT(n)  asm volatile("cp.async.wait_group %0;"::"n"(n):"memory")

// ---------- launch 0: all converts ----------
__global__ void __launch_bounds__(256) cvt_all(const float* __restrict__ x,const float* __restrict__ wq,
        const float* __restrict__ wk,const float* __restrict__ wv,const float* __restrict__ wd,
        const float* __restrict__ mx){
    int bx=blockIdx.x; const float* s; __nv_bfloat16* d; long base;
    if(bx<4096){s=x;d=g_xb;base=bx;}
    else if(bx<5120){s=wq;d=g_Wqb;base=bx-4096;}
    else if(bx<6144){s=wk;d=g_Wkb;base=bx-5120;}
    else if(bx<7168){s=wv;d=g_Wvb;base=bx-6144;}
    else if(bx<8192){s=wd;d=g_Wdb;base=bx-7168;}
    else {s=mx;d=g_mixb;base=bx-8192;}
    size_t off=(size_t)base*1024 + threadIdx.x*4;
    float4 v=*(const float4*)(s+off);
    *(__nv_bfloat162*)(d+off)  =__floats2bfloat162_rn(v.x,v.y);
    *(__nv_bfloat162*)(d+off+2)=__floats2bfloat162_rn(v.z,v.w);
}

// ---------- bf16 GEMM; mode 3 = batched qkv ----------
__global__ void __launch_bounds__(256) gemm_k(const __nv_bfloat16* __restrict__ A,
        const __nv_bfloat16* __restrict__ Bw,const float* __restrict__ bias,
        const float* __restrict__ resid,void* outp,int mode){
    __shared__ __align__(16) __nv_bfloat16 as_[128*72];
    __shared__ __align__(16) __nv_bfloat16 bs_[128*72];
    if(mode==3){
        int z=blockIdx.z;
        Bw=(z==0)?g_Wqb:(z==1)?g_Wkb:g_Wvb;
        outp=(z==0)?(void*)g_q:(z==1)?(void*)g_k:(void*)g_v;
        if(z!=2) bias=nullptr;
        mode=0;
    }
    const int m0=blockIdx.x*128,n0=blockIdx.y*128;
    const int tid=threadIdx.x,wr=tid>>5,ln=tid&31,g=ln>>2,tg=ln&3;
    const unsigned asb=sptr(as_),bsb=sptr(bs_);
    float acc[64];
#pragma unroll
    for(int i=0;i<64;i++) acc[i]=0.f;
    for(int c0=0;c0<1024;c0+=64){
        __syncthreads();
#pragma unroll
        for(int t=0;t<4;t++){
            int idx=tid+t*256,row=idx>>3,cv=(idx&7)*8;
            *(uint4*)((char*)as_+(row*72+cv)*2)=*(const uint4*)(A +(size_t)(m0+row)*1024+c0+cv);
            *(uint4*)((char*)bs_+(row*72+cv)*2)=*(const uint4*)(Bw+(size_t)(n0+row)*1024+c0+cv);
        }
        __syncthreads();
#pragma unroll
        for(int kk=0;kk<4;kk++){
            unsigned a0,a1,a2,a3;
            ldm4(a0,a1,a2,a3,asb+((wr*16+(ln&15))*72+kk*16+((ln>>4)<<3))*2);
#pragma unroll
            for(int nb=0;nb<8;nb++){
                unsigned b0,b1,b2,b3;
                int brow=nb*16+(ln&7)+((ln&16)?8:0),bcol=kk*16+((ln&8)?8:0);
                ldm4(b0,b1,b2,b3,bsb+(brow*72+bcol)*2);
                mma16816(acc+(2*nb  )*4,a0,a1,a2,a3,b0,b1);
                mma16816(acc+(2*nb+1)*4,a0,a1,a2,a3,b2,b3);
            }
        }
    }
    const int r0=m0+wr*16+g;
    if(mode==2){
        float* out=(float*)outp;
#pragma unroll
        for(int nf=0;nf<16;nf++){
            int col=n0+nf*8+2*tg;
            float b0=bias[col],b1=bias[col+1];
            *(float2*)(out+(size_t)r0*1024+col)=make_float2(
                acc[nf*4+0]+b0+resid[(size_t)r0*1024+col],
                acc[nf*4+1]+b1+resid[(size_t)r0*1024+col+1]);
            *(float2*)(out+(size_t)(r0+8)*1024+col)=make_float2(
                acc[nf*4+2]+b0+resid[(size_t)(r0+8)*1024+col],
                acc[nf*4+3]+b1+resid[(size_t)(r0+8)*1024+col+1]);
        }
    }else{
        __nv_bfloat16* out=(__nv_bfloat16*)outp;
#pragma unroll
        for(int nf=0;nf<16;nf++){
            int col=n0+nf*8+2*tg;
            float b0=bias?bias[col]:0.f,b1=bias?bias[col+1]:0.f;
            *(__nv_bfloat162*)(out+(size_t)r0*1024+col)=__floats2bfloat162_rn(acc[nf*4+0]+b0,acc[nf*4+1]+b1);
            *(__nv_bfloat162*)(out+(size_t)(r0+8)*1024+col)=__floats2bfloat162_rn(acc[nf*4+2]+b0,acc[nf*4+3]+b1);
        }
    }
}

// ---------- launch 2: cb + q8mix + k8 ----------
__global__ void __launch_bounds__(256) prep8(const float* __restrict__ x,const float* __restrict__ Wcb){
    int bx=blockIdx.x,tid=threadIdx.x;
    if(bx<4096){
        __shared__ float xr[1024];
        int s=bx;
        for(int t=tid;t<1024;t+=256) xr[t]=x[(size_t)s*1024+t];
        __syncthreads();
        int w=tid>>5,ln=tid&31;
#pragma unroll
        for(int j=0;j<2;j++){
            int h=w*2+j;
            const float* wrow=Wcb+(size_t)h*1024;
            float sum=0.f;
            for(int c=ln;c<1024;c+=32) sum+=xr[c]*wrow[c];
#pragma unroll
            for(int off=16;off;off>>=1) sum+=__shfl_xor_sync(0xffffffffu,sum,off);
            if(ln==0) g_cb[(size_t)s*HH+h]=sum;
        }
    }else if(bx<8192){
        int row=bx-4096, col=tid*4;
        const __nv_bfloat162* q2=(const __nv_bfloat162*)(g_q+(size_t)row*1024+col);
        float2 q0=__bfloat1622float2(q2[0]),q1=__bfloat1622float2(q2[1]);
#pragma unroll
        for(int h=0;h<HH;h++){
            const __nv_bfloat162* m2=(const __nv_bfloat162*)(g_mixb+(size_t)h*1024+col);
            float2 m0=__bfloat1622float2(m2[0]),m1=__bfloat1622float2(m2[1]);
            unsigned p=pk8(q0.x*m0.x,q0.y*m0.y,q1.x*m1.x,q1.y*m1.y);
            *(unsigned*)(g_q8+((size_t)h*4096+row)*1024+col)=p;
        }
    }else{
        size_t off=((size_t)(bx-8192)*256+tid)*4;
        const __nv_bfloat162* k2=(const __nv_bfloat162*)(g_k+off);
        float2 k0=__bfloat1622float2(k2[0]),k1=__bfloat1622float2(k2[1]);
        *(unsigned*)(g_k8+off)=pk8(k0.x,k0.y,k1.x,k1.y);
    }
}

// ---------- launch 3: FP8 flash, 64-row CTA tile, 2 CTAs/SM ----------
#define CHQ  5120u
#define CHK  10240u
#define OQ8  0u
#define OK8  10240u
#define OVS  30720u
#define OPS  49152u
#define OCBS 66560u
#define ORM  67072u
#define ORL  67328u
#define OAL  67584u
#define OPX  67840u
#define FSM  68352

__global__ void __launch_bounds__(256,2) flash_k(){
    extern __shared__ __align__(16) char sm[];
    const int b=blockIdx.z,h=blockIdx.y,i0=blockIdx.x*64;
    const int tid=threadIdx.x,wr=tid>>5,ln=tid&31,g=ln>>2,tg=ln&3;
    const int mg=wr&3,nh=wr>>2;
    const unsigned sb=sptr(sm);
    float* cbs=(float*)(sm+OCBS);
    float* rmS=(float*)(sm+ORM);
    float* rlS=(float*)(sm+ORL);
    float* alS=(float*)(sm+OAL);
    float* px =(float*)(sm+OPX);
    if(tid<64){ rmS[tid]=-1e30f; rlS[tid]=0.f; }
    const unsigned char* q8g=g_q8+((size_t)h*4096+b*2048+i0)*1024;
    const unsigned char* k8g=g_k8+(size_t)(b*2048)*1024;
    const __nv_bfloat16* vg=g_v+(size_t)(b*SS)*DVx;

    float sacc[32],octx[16];
#pragma unroll
    for(int i=0;i<16;i++) octx[i]=0.f;

    auto issue=[&](int j0,int c,int bf){
        int c0=c*64;
        {
            int row=tid>>2,cv=(tid&3)*16;
            cpa16(sb+OQ8+bf*CHQ+(unsigned)(row*80+cv), q8g+(size_t)row*1024+c0+cv);
        }
#pragma unroll
        for(int t=0;t<2;t++){
            int idx=t*256+tid,row=idx>>2,cv=(idx&3)*16;
            cpa16(sb+OK8+bf*CHK+(unsigned)(row*80+cv), k8g+(size_t)(j0+row)*1024+c0+cv);
        }
        CPCOMMIT();
    };
    auto issueV=[&](int j0){
#pragma unroll
        for(int t=0;t<4;t++){
            int idx=t*256+tid,row=idx>>3,cv=(idx&7)*8;
            cpa16(sb+OVS+(unsigned)((row*72+cv)*2), vg+(size_t)(j0+row)*DVx+h*64+cv);
        }
        CPCOMMIT();
    };

    issue(0,0,0); issue(0,1,1);

    for(int jt=0;jt<16;jt++){
        const int j0=jt*128;
#pragma unroll
        for(int i=0;i<32;i++) sacc[i]=0.f;
        for(int c=0;c<16;c++){
            if(c==14){ CPWAIT(2); } else { CPWAIT(1); }
            __syncthreads();
            if(c==0&&tid<128) cbs[tid]=g_cb[(size_t)(b*SS+j0+tid)*HH+h];
            const unsigned qb=sb+OQ8+(unsigned)(c&1)*CHQ, kb=sb+OK8+(unsigned)(c&1)*CHK;
#pragma unroll
            for(int kk=0;kk<2;kk++){
                unsigned a0,a1,a2,a3;
                ldm4(a0,a1,a2,a3,qb+(mg*16+(ln&15))*80+kk*32+((ln>>4)<<4));
#pragma unroll
                for(int nb=0;nb<4;nb++){
                    unsigned b0,b1,b2,b3;
                    int brow=nh*64+nb*16+(ln&7)+((ln&16)?8:0);
                    ldm4(b0,b1,b2,b3,kb+brow*80+kk*32+((ln&8)?16:0));
                    mma16832(sacc+(nb*2  )*4,a0,a1,a2,a3,b0,b1);
                    mma16832(sacc+(nb*2+1)*4,a0,a1,a2,a3,b2,b3);
                }
            }
            __syncthreads();
            if(c<14) issue(j0,c+2,c&1);
            if(c==13) issueV(j0);
        }
        // bias + scale + local rowmax (warp covers 64 cols)
        float lm[2]={-1e30f,-1e30f};
#pragma unroll
        for(int nb=0;nb<4;nb++)
#pragma unroll
        for(int p=0;p<2;p++){
            int col=nh*64+nb*16+p*8+2*tg;
            float cb0=cbs[col],cb1=cbs[col+1];
            float* sp=sacc+(nb*2+p)*4;
            sp[0]=(sp[0]+cb0)*0.125f; sp[1]=(sp[1]+cb1)*0.125f;
            sp[2]=(sp[2]+cb0)*0.125f; sp[3]=(sp[3]+cb1)*0.125f;
            lm[0]=fmaxf(lm[0],fmaxf(sp[0],sp[1]));
            lm[1]=fmaxf(lm[1],fmaxf(sp[2],sp[3]));
        }
#pragma unroll
        for(int hf=0;hf<2;hf++){
            lm[hf]=fmaxf(lm[hf],__shfl_xor_sync(0xffffffffu,lm[hf],1));
            lm[hf]=fmaxf(lm[hf],__shfl_xor_sync(0xffffffffu,lm[hf],2));
            if(tg==0) px[nh*64+mg*16+hf*8+g]=lm[hf];
        }
        __syncthreads();
        if(nh==0&&tg==0){
#pragma unroll
            for(int hf=0;hf<2;hf++){
                int row=mg*16+hf*8+g;
                float mn=fmaxf(rmS[row],fmaxf(px[row],px[64+row]));
                alS[row]=exp2f((rmS[row]-mn)*LOG2E);
                rmS[row]=mn;
            }
        }
        __syncthreads();
        // exp, row sums, pack P -> smem
        float ls[2]={0.f,0.f};
        {
            int r0=mg*16+g;
            float mx0=rmS[r0],mx1=rmS[r0+8];
#pragma unroll
            for(int nb=0;nb<4;nb++)
#pragma unroll
            for(int p=0;p<2;p++){
                float* sp=sacc+(nb*2+p)*4;
                sp[0]=exp2f((sp[0]-mx0)*LOG2E); sp[1]=exp2f((sp[1]-mx0)*LOG2E);
                sp[2]=exp2f((sp[2]-mx1)*LOG2E); sp[3]=exp2f((sp[3]-mx1)*LOG2E);
                ls[0]+=sp[0]+sp[1]; ls[1]+=sp[2]+sp[3];
                int col=nh*64+nb*16+p*8+2*tg;
                *(unsigned*)(sm+OPS+((size_t)r0*136+col)*2)    =pack2(sp[0],sp[1]);
                *(unsigned*)(sm+OPS+((size_t)(r0+8)*136+col)*2)=pack2(sp[2],sp[3]);
            }
        }
#pragma unroll
        for(int hf=0;hf<2;hf++){
            ls[hf]+=__shfl_xor_sync(0xffffffffu,ls[hf],1);
            ls[hf]+=__shfl_xor_sync(0xffffffffu,ls[hf],2);
            if(tg==0) px[nh*64+mg*16+hf*8+g]=ls[hf];
        }
        __syncthreads();
        if(nh==0&&tg==0){
#pragma unroll
            for(int hf=0;hf<2;hf++){
                int row=mg*16+hf*8+g;
                rlS[row]=rlS[row]*alS[row]+px[row]+px[64+row];
            }
        }
        __syncthreads();
        // rescale octx
        {
            float a0=alS[mg*16+g],a1=alS[mg*16+8+g];
#pragma unroll
            for(int i=0;i<4;i++){
                octx[i*4+0]*=a0; octx[i*4+1]*=a0;
                octx[i*4+2]*=a1; octx[i*4+3]*=a1;
            }
        }
        CPWAIT(0);
        __syncthreads();
        // PV: warp = 16 rows x 32 v-cols
#pragma unroll
        for(int kb2=0;kb2<8;kb2++){
            unsigned p0,p1,p2,p3;
            ldm4(p0,p1,p2,p3,sb+OPS+((mg*16+(ln&15))*136+kb2*16+((ln>>4)<<3))*2);
#pragma unroll
            for(int vp=0;vp<2;vp++){
                unsigned b0,b1,b2,b3;
                int vrow=kb2*16+(ln&7)+((ln&8)?8:0);
                int vcol=nh*32+vp*16+((ln&16)?8:0);
                ldm4t(b0,b1,b2,b3,sb+OVS+(vrow*72+vcol)*2);
                mma16816(octx+(2*vp  )*4,p0,p1,p2,p3,b0,b1);
                mma16816(octx+(2*vp+1)*4,p0,p1,p2,p3,b2,b3);
            }
        }
        __syncthreads();
        if(jt<15){ issue(j0+128,0,0); issue(j0+128,1,1); }
    }
    float inv0=1.f/rlS[mg*16+g],inv1=1.f/rlS[mg*16+8+g];
    int r0=i0+mg*16+g;
    __nv_bfloat16* cg=g_ctx+(size_t)(b*SS)*DVx+h*64;
#pragma unroll
    for(int i=0;i<4;i++){
        int col=nh*32+i*8+2*tg;
        *(__nv_bfloat162*)(cg+(size_t)r0*DVx+col)=
            __floats2bfloat162_rn(octx[i*4+0]*inv0,octx[i*4+1]*inv0);
        *(__nv_bfloat162*)(cg+(size_t)(r0+8)*DVx+col)=
            __floats2bfloat162_rn(octx[i*4+2]*inv1,octx[i*4+3]*inv1);
    }
}

__global__ void __launch_bounds__(256) ln_k(const float* __restrict__ gamma,
        const float* __restrict__ beta,float* __restrict__ out){
    int s=blockIdx.x,tid=threadIdx.x;
    const float* r=g_res+(size_t)s*1024;
    float sum=0.f,sq=0.f;
#pragma unroll
    for(int i=tid;i<1024;i+=256){ float v=r[i]; sum+=v; sq+=v*v; }
#pragma unroll
    for(int off=16;off;off>>=1){
        sum+=__shfl_xor_sync(0xffffffffu,sum,off);
        sq +=__shfl_xor_sync(0xffffffffu,sq ,off);
    }
    __shared__ float ss[8],sv[8];
    if((tid&31)==0){ ss[tid>>5]=sum; sv[tid>>5]=sq; }
    __syncthreads();
    float tot=0.f,tot2=0.f;
#pragma unroll
    for(int i=0;i<8;i++){ tot+=ss[i]; tot2+=sv[i]; }
    float mu=tot*(1.f/1024.f),var=tot2*(1.f/1024.f)-mu*mu;
    float is=rsqrtf(var+1e-5f);
    for(int i=tid;i<1024;i+=256)
        out[(size_t)s*1024+i]=(r[i]-mu)*is*gamma[i]+beta[i];
}

extern "C" void kernel_launch(void* const* d_in,const int* in_sizes,int n_in,
                              void* d_out,int out_size){
    const float* x    =(const float*)d_in[0];
    const float* Wq   =(const float*)d_in[1];
    const float* Wk   =(const float*)d_in[2];
    const float* Wcb  =(const float*)d_in[3];
    const float* Wv   =(const float*)d_in[4];
    const float* bv   =(const float*)d_in[5];
    const float* mixing=(const float*)d_in[6];
    const float* Wd   =(const float*)d_in[7];
    const float* bd   =(const float*)d_in[8];
    const float* gamma=(const float*)d_in[9];
    const float* beta =(const float*)d_in[10];
    float* out=(float*)d_out;

    void *xb,*wdb,*ctxb,*resp;
    cudaGetSymbolAddress(&xb ,g_xb ); cudaGetSymbolAddress(&wdb,g_Wdb);
    cudaGetSymbolAddress(&ctxb,g_ctx); cudaGetSymbolAddress(&resp,g_res);

    cudaFuncSetAttribute(flash_k,cudaFuncAttributeMaxDynamicSharedMemorySize,FSM);

    cvt_all<<<8208,256>>>(x,Wq,Wk,Wv,Wd,mixing);                        // 0
    gemm_k<<<dim3(32,8,3),256>>>((const __nv_bfloat16*)xb,nullptr,bv,nullptr,nullptr,3); // 1
    prep8<<<12288,256>>>(x,Wcb);                                        // 2
    flash_k<<<dim3(32,HH,BB),256,FSM>>>();                              // 3 <- profiled
    gemm_k<<<dim3(32,8),256>>>((const __nv_bfloat16*)ctxb,(const __nv_bfloat16*)wdb,bd,x,resp,2); // 4
    ln_k<<<BSx,256>>>(gamma,beta,out);                                  // 5
}